// round 4
// baseline (speedup 1.0000x reference)
#include <cuda_runtime.h>
#include <math.h>
#include <stdint.h>

// Problem constants
#define BQ 2
#define CQ 128
#define TQ 32
#define NQ 512
#define PQ (TQ * NQ)      // 16384 points per batch
#define KQ 16
#define HIDQ 512
#define OUTC 132
#define THREEN 1536

// ---------------------------------------------------------------------------
// Device scratch (static — no allocations allowed)
// ---------------------------------------------------------------------------
__device__ float g_xpm[BQ * PQ * CQ];      // x transposed to (b,p,c), full precision (residual)
__device__ float g_xtf[BQ * PQ * CQ];      // x transposed, tf32-rounded (QKV GEMM input)
__device__ float g_qkv[BQ * PQ * 384];     // (b, p, [q(128) | kx(128) | vx(128)])
__device__ int   g_idx[BQ * PQ * KQ];      // neighbor composite index t_eff*N + n'
__device__ float g_h[BQ * PQ * CQ];        // post-attn+BN h, tf32-rounded (MLP input)
__device__ float g_wq[CQ * CQ], g_wk[CQ * CQ], g_wv[CQ * CQ];   // rounded weights
__device__ float g_w1[HIDQ * CQ], g_w2[CQ * HIDQ];

// ---------------------------------------------------------------------------
// tf32 / async helpers
// ---------------------------------------------------------------------------
__device__ __forceinline__ uint32_t f2tf(float f)
{
    uint32_t r;
    asm("cvt.rna.tf32.f32 %0, %1;" : "=r"(r) : "f"(f));
    return r;
}
__device__ __forceinline__ float f2tff(float f) { return __uint_as_float(f2tf(f)); }

__device__ __forceinline__ void mma_tf32(float c[4],
                                         uint32_t a0, uint32_t a1, uint32_t a2, uint32_t a3,
                                         uint32_t b0, uint32_t b1)
{
    asm volatile(
        "mma.sync.aligned.m16n8k8.row.col.f32.tf32.tf32.f32 "
        "{%0,%1,%2,%3},{%4,%5,%6,%7},{%8,%9},{%0,%1,%2,%3};"
        : "+f"(c[0]), "+f"(c[1]), "+f"(c[2]), "+f"(c[3])
        : "r"(a0), "r"(a1), "r"(a2), "r"(a3), "r"(b0), "r"(b1));
}

__device__ __forceinline__ void cp16(uint32_t* dst_smem, const float* src)
{
    uint32_t d = (uint32_t)__cvta_generic_to_shared(dst_smem);
    asm volatile("cp.async.cg.shared.global [%0], [%1], 16;" :: "r"(d), "l"(src));
}
__device__ __forceinline__ void cp_commit() { asm volatile("cp.async.commit_group;" ::: "memory"); }
template<int N>
__device__ __forceinline__ void cp_wait() { asm volatile("cp.async.wait_group %0;" :: "n"(N) : "memory"); }

// ---------------------------------------------------------------------------
// K_pre: round all weights to tf32 once.
// ---------------------------------------------------------------------------
__global__ void k_roundw(const float* __restrict__ Wq, const float* __restrict__ Wk,
                         const float* __restrict__ Wv, const float* __restrict__ W1,
                         const float* __restrict__ W2)
{
    int i = blockIdx.x * 256 + threadIdx.x;   // 0 .. 65535
    if (i < CQ * CQ) {
        g_wq[i] = f2tff(Wq[i]);
        g_wk[i] = f2tff(Wk[i]);
        g_wv[i] = f2tff(Wv[i]);
    }
    g_w1[i] = f2tff(W1[i]);
    g_w2[i] = f2tff(W2[i]);
}

// ---------------------------------------------------------------------------
// K0: transpose x (B,C,P) -> g_xpm (full) and g_xtf (tf32-rounded), (B,P,C)
// ---------------------------------------------------------------------------
__global__ void k_transpose(const float* __restrict__ x)
{
    __shared__ float tile[32][33];
    int b = blockIdx.z;
    int p0 = blockIdx.x * 32;
    int c0 = blockIdx.y * 32;
    const float* xb = x + (size_t)b * CQ * PQ;
    int tx = threadIdx.x, ty = threadIdx.y;
#pragma unroll
    for (int i = 0; i < 32; i += 8)
        tile[ty + i][tx] = xb[(size_t)(c0 + ty + i) * PQ + p0 + tx];
    __syncthreads();
    float* op  = g_xpm + (size_t)b * PQ * CQ;
    float* op2 = g_xtf + (size_t)b * PQ * CQ;
#pragma unroll
    for (int i = 0; i < 32; i += 8) {
        float v = tile[tx][ty + i];
        size_t o = (size_t)(p0 + ty + i) * CQ + c0 + tx;
        op[o]  = v;
        op2[o] = f2tff(v);
    }
}

// ---------------------------------------------------------------------------
// K1: top-K neighbor selection (unchanged — correct & cheap).
// ---------------------------------------------------------------------------
__global__ void __launch_bounds__(256) k_topk(const float* __restrict__ x)
{
    int t = blockIdx.x, b = blockIdx.y, z = blockIdx.z;
    __shared__ float sc[3][THREEN];
    const float* xb = x + (size_t)b * CQ * PQ;
    int tid = threadIdx.x;

    for (int i = tid; i < 3 * THREEN; i += 256) {
        int c = i / THREEN, m = i % THREEN;
        int j = m >> 9, nn = m & 511;
        int te = t - 1 + j;
        te = te < 0 ? 0 : (te > TQ - 1 ? TQ - 1 : te);
        sc[c][m] = xb[(size_t)c * PQ + te * NQ + nn];
    }
    __syncthreads();

    int lane = tid & 31, w = tid >> 5;
    for (int i = 0; i < 8; i++) {
        int n = z * 64 + w * 8 + i;
        float a0 = sc[0][512 + n], a1 = sc[1][512 + n], a2 = sc[2][512 + n];
        float d[48];
#pragma unroll
        for (int jj = 0; jj < 48; jj++) {
            int m = jj * 32 + lane;
            float dx = sc[0][m] - a0;
            float dy = sc[1][m] - a1;
            float dz = sc[2][m] - a2;
            d[jj] = dx * dx + dy * dy + dz * dz;
        }
        unsigned long long removed = 0ull;
        int* orow = g_idx + ((size_t)(b * TQ + t) * NQ + n) * KQ;
        for (int it = 0; it < KQ; it++) {
            float best = 3.4e38f;
            int bj = 0;
#pragma unroll
            for (int jj = 0; jj < 48; jj++) {
                bool alive = !(removed & (1ull << jj));
                if (alive && d[jj] < best) { best = d[jj]; bj = jj; }
            }
            int bm = bj * 32 + lane;
#pragma unroll
            for (int off = 16; off; off >>= 1) {
                float od = __shfl_xor_sync(0xffffffffu, best, off);
                int   om = __shfl_xor_sync(0xffffffffu, bm, off);
                if (od < best || (od == best && om < bm)) { best = od; bm = om; }
            }
            if ((bm & 31) == lane) removed |= (1ull << (bm >> 5));
            if (lane == 0) {
                int jwin = bm >> 9, nwin = bm & 511;
                int te = t - 1 + jwin;
                te = te < 0 ? 0 : (te > TQ - 1 ? TQ - 1 : te);
                orow[it] = te * NQ + nwin;
            }
        }
    }
}

// ---------------------------------------------------------------------------
// Uniform tf32 GEMM core (unchanged from round 3): 128x128 block, KC=16,
// 2-stage cp.async double buffer.
// ---------------------------------------------------------------------------
template<int CIN>
__device__ __forceinline__ void gemm_core(const float* __restrict__ A,
                                          const float* __restrict__ W,
                                          float acc[4][4][4], int tid)
{
    constexpr int KC = 16;
    constexpr int NCH = CIN / KC;
    __shared__ uint32_t As[2][128 * 20];
    __shared__ uint32_t Bs[2][128 * 20];

    const int lane = tid & 31, wid = tid >> 5;
    const int gid = lane >> 2, tig = lane & 3;
    const int mbase = (wid & 1) * 64, nbase = (wid >> 1) * 32;

    const int r0 = tid >> 2, s0 = (tid & 3) * 4;
    const int r1 = (tid + 256) >> 2, s1 = s0;

    {
        cp16(&As[0][r0 * 20 + s0], A + (size_t)r0 * CIN + s0);
        cp16(&As[0][r1 * 20 + s1], A + (size_t)r1 * CIN + s1);
        cp16(&Bs[0][r0 * 20 + s0], W + (size_t)r0 * CIN + s0);
        cp16(&Bs[0][r1 * 20 + s1], W + (size_t)r1 * CIN + s1);
        cp_commit();
    }

#pragma unroll 1
    for (int kc = 0; kc < NCH; kc++) {
        const int st = kc & 1;
        if (kc + 1 < NCH) {
            const int k0g = (kc + 1) * KC;
            cp16(&As[st ^ 1][r0 * 20 + s0], A + (size_t)r0 * CIN + k0g + s0);
            cp16(&As[st ^ 1][r1 * 20 + s1], A + (size_t)r1 * CIN + k0g + s1);
            cp16(&Bs[st ^ 1][r0 * 20 + s0], W + (size_t)r0 * CIN + k0g + s0);
            cp16(&Bs[st ^ 1][r1 * 20 + s1], W + (size_t)r1 * CIN + k0g + s1);
            cp_commit();
            cp_wait<1>();
        } else {
            cp_commit();
            cp_wait<0>();
        }
        __syncthreads();

#pragma unroll
        for (int ks = 0; ks < 2; ks++) {
            const int k0 = ks * 8;
            uint32_t af[4][4], bf[4][2];
#pragma unroll
            for (int mt = 0; mt < 4; mt++) {
                int m = mbase + mt * 16 + gid;
                af[mt][0] = As[st][m * 20 + k0 + tig];
                af[mt][1] = As[st][(m + 8) * 20 + k0 + tig];
                af[mt][2] = As[st][m * 20 + k0 + 4 + tig];
                af[mt][3] = As[st][(m + 8) * 20 + k0 + 4 + tig];
            }
#pragma unroll
            for (int nt = 0; nt < 4; nt++) {
                int n = nbase + nt * 8 + gid;
                bf[nt][0] = Bs[st][n * 20 + k0 + tig];
                bf[nt][1] = Bs[st][n * 20 + k0 + 4 + tig];
            }
#pragma unroll
            for (int mt = 0; mt < 4; mt++)
#pragma unroll
                for (int nt = 0; nt < 4; nt++)
                    mma_tf32(acc[mt][nt], af[mt][0], af[mt][1], af[mt][2], af[mt][3],
                             bf[nt][0], bf[nt][1]);
        }
        __syncthreads();
    }
}

// K2: fused QKV projection. grid (128, 3, B).
__global__ void __launch_bounds__(256) k_gemm_qkv()
{
    int b = blockIdx.z;
    int p0 = blockIdx.x * 128;
    int cq = blockIdx.y;
    const float* W = (cq == 0) ? g_wq : ((cq == 1) ? g_wk : g_wv);

    float acc[4][4][4] = {};
    gemm_core<CQ>(g_xtf + (size_t)(b * PQ + p0) * CQ, W, acc, threadIdx.x);

    const int lane = threadIdx.x & 31, wid = threadIdx.x >> 5;
    const int gid = lane >> 2, tig = lane & 3;
    float* base = g_qkv + (size_t)(b * PQ + p0 + (wid & 1) * 64) * 384 + cq * 128 + (wid >> 1) * 32;
#pragma unroll
    for (int mt = 0; mt < 4; mt++) {
        int r = mt * 16 + gid;
#pragma unroll
        for (int nt = 0; nt < 4; nt++) {
            int c = nt * 8 + tig * 2;
            *(float2*)(base + (size_t)r * 384 + c)       = make_float2(acc[mt][nt][0], acc[mt][nt][1]);
            *(float2*)(base + (size_t)(r + 8) * 384 + c) = make_float2(acc[mt][nt][2], acc[mt][nt][3]);
        }
    }
}

// ---------------------------------------------------------------------------
// K3: attention + residual + BN. Writes h pre-rounded to tf32. (unchanged)
// ---------------------------------------------------------------------------
__global__ void __launch_bounds__(256) k_attn(const float* __restrict__ gamma,
                                              const float* __restrict__ beta,
                                              const float* __restrict__ mean,
                                              const float* __restrict__ var)
{
    __shared__ float s_scale[CQ], s_shift[CQ];
    int tid = threadIdx.x;
    if (tid < CQ) {
        float sc = gamma[tid] * rsqrtf(var[tid] + 1e-5f);
        s_scale[tid] = sc;
        s_shift[tid] = beta[tid] - mean[tid] * sc;
    }
    __syncthreads();

    int lane = tid & 31, w = tid >> 5;
    const float rs = 0.17677669529663687f; // 1/sqrt(32)

    for (int i = 0; i < 8; i++) {
        int g = blockIdx.x * 64 + w * 8 + i;
        int b = g >> 14;
        int bbase = b << 14;

        const float4* qk = (const float4*)(g_qkv + (size_t)g * 384);
        float4 qv = qk[lane];
        float4 ks = qk[32 + lane];
        float4 vs = qk[64 + lane];

        const int* irow = g_idx + (size_t)g * KQ;
        int myidx = irow[lane & 15];

        float dself;
        {
            float p = qv.x * ks.x + qv.y * ks.y + qv.z * ks.z + qv.w * ks.w;
            p += __shfl_xor_sync(0xffffffffu, p, 1);
            p += __shfl_xor_sync(0xffffffffu, p, 2);
            p += __shfl_xor_sync(0xffffffffu, p, 4);
            dself = p;
        }

        float e[16];
#pragma unroll
        for (int k = 0; k < 16; k++) {
            int nb = __shfl_sync(0xffffffffu, myidx, k);
            const float4* kp = (const float4*)(g_qkv + (size_t)(bbase + nb) * 384 + 128);
            float4 kn = kp[lane];
            float p = qv.x * kn.x + qv.y * kn.y + qv.z * kn.z + qv.w * kn.w;
            p += __shfl_xor_sync(0xffffffffu, p, 1);
            p += __shfl_xor_sync(0xffffffffu, p, 2);
            p += __shfl_xor_sync(0xffffffffu, p, 4);
            e[k] = (dself - p) * rs;
        }

        float mx = e[0];
#pragma unroll
        for (int k = 1; k < 16; k++) mx = fmaxf(mx, e[k]);
        float s = 0.f;
#pragma unroll
        for (int k = 0; k < 16; k++) { e[k] = expf(e[k] - mx); s += e[k]; }
        float inv = 1.0f / s;

        float4 acc = vs;
#pragma unroll
        for (int k = 0; k < 16; k++) {
            int nb = __shfl_sync(0xffffffffu, myidx, k);
            const float4* vp = (const float4*)(g_qkv + (size_t)(bbase + nb) * 384 + 256);
            float4 vn = vp[lane];
            float a = e[k] * inv;
            acc.x -= a * vn.x; acc.y -= a * vn.y;
            acc.z -= a * vn.z; acc.w -= a * vn.w;
        }

        const float4* xp = (const float4*)(g_xpm + (size_t)g * CQ);
        float4 xv = xp[lane];
        int c = lane * 4;
        float4 hv;
        hv.x = f2tff((xv.x + acc.x) * s_scale[c + 0] + s_shift[c + 0]);
        hv.y = f2tff((xv.y + acc.y) * s_scale[c + 1] + s_shift[c + 1]);
        hv.z = f2tff((xv.z + acc.z) * s_scale[c + 2] + s_shift[c + 2]);
        hv.w = f2tff((xv.w + acc.w) * s_scale[c + 3] + s_shift[c + 3]);
        ((float4*)(g_h + (size_t)g * CQ))[lane] = hv;
    }
}

// ---------------------------------------------------------------------------
// K4: fused MLP  y = W2 @ leaky(W1 @ h)  — no hid round-trip to DRAM.
// Block: 64 points (M), 128 outputs (N2). hid processed in 4 chunks of 128:
//   stage A: hidS = tf32(leaky(h_tile @ W1_chunk^T))   (into smem)
//   stage B: acc2 += hidS @ W2_chunk^T
// W sub-tiles (128x32) stream via 2-stage cp.async (32 units total).
// smem: hS 64x132 + hidS 64x132 + Ws 2x128x36  = 104448 B (dynamic).
// ---------------------------------------------------------------------------
#define MLP_SMEM ((2 * 64 * 132 + 2 * 128 * 36) * 4)

__global__ void __launch_bounds__(256, 2) k_mlp(float* __restrict__ out)
{
    extern __shared__ uint32_t smem[];
    uint32_t* hS   = smem;                    // [64][132]
    uint32_t* hidS = smem + 64 * 132;         // [64][132]
    uint32_t* Ws   = smem + 2 * 64 * 132;     // [2][128][36]

    const int b = blockIdx.z;
    const int p0 = blockIdx.x * 64;
    const float* hbase = g_h + (size_t)(b * PQ + p0) * CQ;

    const int tid = threadIdx.x;
    const int lane = tid & 31, wid = tid >> 5;
    const int gid = lane >> 2, tig = lane & 3;
    const int mbase = (wid & 1) * 32;
    const int nbase = (wid >> 1) * 32;

    // load h tile (64 rows x 128 words) once
    {
        int seg = tid & 31;
        int r = tid >> 5;
#pragma unroll
        for (int it = 0; it < 8; it++, r += 8)
            cp16(&hS[r * 132 + seg * 4], hbase + (size_t)r * CQ + seg * 4);
    }

    // W prefetch helper (unit u: c = u>>3, stageB = (u>>2)&1, kc4 = u&3)
    const int wseg = tid & 7;
    const int wr0 = tid >> 3;
#define PREFETCH_W(u, buf)                                                        \
    {                                                                             \
        int c_ = (u) >> 3, kc4_ = (u) & 3;                                        \
        bool sb_ = ((u) >> 2) & 1;                                                \
        uint32_t* dst = Ws + (buf) * (128 * 36);                                  \
        int r_ = wr0;                                                             \
        _Pragma("unroll")                                                         \
        for (int it_ = 0; it_ < 4; it_++, r_ += 32) {                             \
            const float* src = sb_                                                \
                ? g_w2 + (size_t)r_ * HIDQ + c_ * 128 + kc4_ * 32 + wseg * 4      \
                : g_w1 + (size_t)(c_ * 128 + r_) * CQ + kc4_ * 32 + wseg * 4;     \
            cp16(&dst[r_ * 36 + wseg * 4], src);                                  \
        }                                                                         \
    }

    PREFETCH_W(0, 0);
    cp_commit();

    float acc1[2][4][4] = {};   // stage A accumulator (64x128 across block)
    float acc2[2][4][4] = {};   // final outputs (64x128 across block)

#pragma unroll 1
    for (int u = 0; u < 32; u++) {
        cp_wait<0>();
        __syncthreads();
        if (u + 1 < 32) {
            PREFETCH_W(u + 1, (u + 1) & 1);
            cp_commit();
        }

        const bool stageB = (u >> 2) & 1;
        const int kc4 = u & 3;
        const uint32_t* A = stageB ? hidS : hS;
        const uint32_t* Wb = Ws + (u & 1) * (128 * 36);
        float (*acc)[4][4] = stageB ? acc2 : acc1;

#pragma unroll
        for (int ks = 0; ks < 4; ks++) {
            const int k0 = kc4 * 32 + ks * 8;
            uint32_t af[2][4], bf[4][2];
#pragma unroll
            for (int mt = 0; mt < 2; mt++) {
                int m = mbase + mt * 16 + gid;
                af[mt][0] = A[m * 132 + k0 + tig];
                af[mt][1] = A[(m + 8) * 132 + k0 + tig];
                af[mt][2] = A[m * 132 + k0 + 4 + tig];
                af[mt][3] = A[(m + 8) * 132 + k0 + 4 + tig];
            }
#pragma unroll
            for (int nt = 0; nt < 4; nt++) {
                int n = nbase + nt * 8 + gid;
                bf[nt][0] = Wb[n * 36 + ks * 8 + tig];
                bf[nt][1] = Wb[n * 36 + ks * 8 + 4 + tig];
            }
#pragma unroll
            for (int mt = 0; mt < 2; mt++)
#pragma unroll
                for (int nt = 0; nt < 4; nt++)
                    mma_tf32(acc[mt][nt], af[mt][0], af[mt][1], af[mt][2], af[mt][3],
                             bf[nt][0], bf[nt][1]);
        }

        if ((u & 7) == 3) {
            // end of stage A for this chunk: leaky + tf32-round -> hidS, reset acc1
#pragma unroll
            for (int mt = 0; mt < 2; mt++) {
                int m0 = mbase + mt * 16 + gid;
#pragma unroll
                for (int nt = 0; nt < 4; nt++) {
                    int j = nbase + nt * 8 + tig * 2;
                    float v0 = acc1[mt][nt][0], v1 = acc1[mt][nt][1];
                    float v2 = acc1[mt][nt][2], v3 = acc1[mt][nt][3];
                    hidS[m0 * 132 + j]           = f2tf(v0 > 0.f ? v0 : 0.2f * v0);
                    hidS[m0 * 132 + j + 1]       = f2tf(v1 > 0.f ? v1 : 0.2f * v1);
                    hidS[(m0 + 8) * 132 + j]     = f2tf(v2 > 0.f ? v2 : 0.2f * v2);
                    hidS[(m0 + 8) * 132 + j + 1] = f2tf(v3 > 0.f ? v3 : 0.2f * v3);
                    acc1[mt][nt][0] = 0.f; acc1[mt][nt][1] = 0.f;
                    acc1[mt][nt][2] = 0.f; acc1[mt][nt][3] = 0.f;
                }
            }
            // visibility of hidS guaranteed by the __syncthreads at next iter top
        }
    }

    // epilogue: acc2 -> out channel-major at channel offset 4
    float* ob = out + (size_t)b * OUTC * PQ + (size_t)4 * PQ;
#pragma unroll
    for (int mt = 0; mt < 2; mt++) {
        int r = p0 + mbase + mt * 16 + gid;
#pragma unroll
        for (int nt = 0; nt < 4; nt++) {
            int c = nbase + nt * 8 + tig * 2;
            ob[(size_t)c * PQ + r]           = acc2[mt][nt][0];
            ob[(size_t)(c + 1) * PQ + r]     = acc2[mt][nt][1];
            ob[(size_t)c * PQ + r + 8]       = acc2[mt][nt][2];
            ob[(size_t)(c + 1) * PQ + r + 8] = acc2[mt][nt][3];
        }
    }
#undef PREFETCH_W
}

// ---------------------------------------------------------------------------
extern "C" void kernel_launch(void* const* d_in, const int* in_sizes, int n_in,
                              void* d_out, int out_size)
{
    const float* x     = (const float*)d_in[0];
    const float* Wq    = (const float*)d_in[1];
    const float* Wk    = (const float*)d_in[2];
    const float* Wv    = (const float*)d_in[3];
    const float* W1    = (const float*)d_in[4];
    const float* W2    = (const float*)d_in[5];
    const float* gamma = (const float*)d_in[6];
    const float* beta  = (const float*)d_in[7];
    const float* mean  = (const float*)d_in[8];
    const float* var   = (const float*)d_in[9];
    float* out = (float*)d_out;

    cudaFuncSetAttribute(k_mlp, cudaFuncAttributeMaxDynamicSharedMemorySize, MLP_SMEM);

    k_roundw<<<256, 256>>>(Wq, Wk, Wv, W1, W2);
    k_transpose<<<dim3(PQ / 32, CQ / 32, BQ), dim3(32, 8)>>>(x);
    k_topk<<<dim3(TQ, BQ, 8), 256>>>(x);
    k_gemm_qkv<<<dim3(PQ / 128, 3, BQ), 256>>>();
    k_attn<<<dim3((BQ * PQ) / 64, 1, 1), 256>>>(gamma, beta, mean, var);
    k_mlp<<<dim3(PQ / 64, 1, BQ), 256, MLP_SMEM>>>(out);

    for (int b = 0; b < BQ; b++) {
        cudaMemcpyAsync(out + (size_t)b * OUTC * PQ,
                        x + (size_t)b * CQ * PQ,
                        (size_t)4 * PQ * sizeof(float),
                        cudaMemcpyDeviceToDevice);
    }
}

// round 5
// speedup vs baseline: 1.4853x; 1.4853x over previous
#include <cuda_runtime.h>
#include <math.h>
#include <stdint.h>

// Problem constants
#define BQ 2
#define CQ 128
#define TQ 32
#define NQ 512
#define PQ (TQ * NQ)      // 16384 points per batch
#define KQ 16
#define HIDQ 512
#define OUTC 132
#define THREEN 1536

// ---------------------------------------------------------------------------
// Device scratch (static — no allocations allowed)
// ---------------------------------------------------------------------------
__device__ float g_xpm[BQ * PQ * CQ];      // x transposed to (b,p,c), full precision (residual)
__device__ float g_xtf[BQ * PQ * CQ];      // x transposed, tf32-rounded (QKV GEMM input)
__device__ float g_qkv[BQ * PQ * 384];     // (b, p, [q(128) | kx(128) | vx(128)])
__device__ int   g_idx[BQ * PQ * KQ];      // neighbor composite index t_eff*N + n'
__device__ float g_h[BQ * PQ * CQ];        // post-attn+BN h, tf32-rounded (W1 input)
__device__ float g_hid[BQ * PQ * HIDQ];    // leaky(W1@h), tf32-rounded (W2 input)
__device__ float g_wq[CQ * CQ], g_wk[CQ * CQ], g_wv[CQ * CQ];   // rounded weights
__device__ float g_w1[HIDQ * CQ], g_w2[CQ * HIDQ];

// ---------------------------------------------------------------------------
// tf32 / async helpers
// ---------------------------------------------------------------------------
__device__ __forceinline__ uint32_t f2tf(float f)
{
    uint32_t r;
    asm("cvt.rna.tf32.f32 %0, %1;" : "=r"(r) : "f"(f));
    return r;
}
__device__ __forceinline__ float f2tff(float f) { return __uint_as_float(f2tf(f)); }

__device__ __forceinline__ void mma_tf32(float c[4],
                                         uint32_t a0, uint32_t a1, uint32_t a2, uint32_t a3,
                                         uint32_t b0, uint32_t b1)
{
    asm volatile(
        "mma.sync.aligned.m16n8k8.row.col.f32.tf32.tf32.f32 "
        "{%0,%1,%2,%3},{%4,%5,%6,%7},{%8,%9},{%0,%1,%2,%3};"
        : "+f"(c[0]), "+f"(c[1]), "+f"(c[2]), "+f"(c[3])
        : "r"(a0), "r"(a1), "r"(a2), "r"(a3), "r"(b0), "r"(b1));
}

__device__ __forceinline__ void cp16(uint32_t* dst_smem, const float* src)
{
    uint32_t d = (uint32_t)__cvta_generic_to_shared(dst_smem);
    asm volatile("cp.async.cg.shared.global [%0], [%1], 16;" :: "r"(d), "l"(src));
}
__device__ __forceinline__ void cp_commit() { asm volatile("cp.async.commit_group;" ::: "memory"); }
template<int N>
__device__ __forceinline__ void cp_wait() { asm volatile("cp.async.wait_group %0;" :: "n"(N) : "memory"); }

// ---------------------------------------------------------------------------
// K_pre: round all weights to tf32 once.
// ---------------------------------------------------------------------------
__global__ void k_roundw(const float* __restrict__ Wq, const float* __restrict__ Wk,
                         const float* __restrict__ Wv, const float* __restrict__ W1,
                         const float* __restrict__ W2)
{
    int i = blockIdx.x * 256 + threadIdx.x;   // 0 .. 65535
    if (i < CQ * CQ) {
        g_wq[i] = f2tff(Wq[i]);
        g_wk[i] = f2tff(Wk[i]);
        g_wv[i] = f2tff(Wv[i]);
    }
    g_w1[i] = f2tff(W1[i]);
    g_w2[i] = f2tff(W2[i]);
}

// ---------------------------------------------------------------------------
// K0: transpose x (B,C,P) -> g_xpm (full) and g_xtf (tf32-rounded), (B,P,C)
// ---------------------------------------------------------------------------
__global__ void k_transpose(const float* __restrict__ x)
{
    __shared__ float tile[32][33];
    int b = blockIdx.z;
    int p0 = blockIdx.x * 32;
    int c0 = blockIdx.y * 32;
    const float* xb = x + (size_t)b * CQ * PQ;
    int tx = threadIdx.x, ty = threadIdx.y;
#pragma unroll
    for (int i = 0; i < 32; i += 8)
        tile[ty + i][tx] = xb[(size_t)(c0 + ty + i) * PQ + p0 + tx];
    __syncthreads();
    float* op  = g_xpm + (size_t)b * PQ * CQ;
    float* op2 = g_xtf + (size_t)b * PQ * CQ;
#pragma unroll
    for (int i = 0; i < 32; i += 8) {
        float v = tile[tx][ty + i];
        size_t o = (size_t)(p0 + ty + i) * CQ + c0 + tx;
        op[o]  = v;
        op2[o] = f2tff(v);
    }
}

// ---------------------------------------------------------------------------
// K1: top-K neighbor selection — FAST PATH:
//   1) per lane: branchless register-sorted top-5 of its 48 candidates,
//      64-bit keys (d_bits << 32 | m) give exact (d, index) lexicographic order
//   2) 16-round warp merge of lane heads (u64 shuffle-min)
//   3) exact fallback (old masked argmin) if any lane exhausted its 5 slots
// Semantics identical to jax.lax.top_k(-d2, 16) incl. tie-breaking.
// ---------------------------------------------------------------------------
__global__ void __launch_bounds__(256) k_topk(const float* __restrict__ x)
{
    int t = blockIdx.x, b = blockIdx.y, z = blockIdx.z;
    __shared__ float sc[3][THREEN];
    const float* xb = x + (size_t)b * CQ * PQ;
    int tid = threadIdx.x;

    for (int i = tid; i < 3 * THREEN; i += 256) {
        int c = i / THREEN, m = i % THREEN;
        int j = m >> 9, nn = m & 511;
        int te = t - 1 + j;
        te = te < 0 ? 0 : (te > TQ - 1 ? TQ - 1 : te);
        sc[c][m] = xb[(size_t)c * PQ + te * NQ + nn];
    }
    __syncthreads();

    const unsigned FULL = 0xffffffffu;
    int lane = tid & 31, w = tid >> 5;

    for (int i = 0; i < 8; i++) {
        int n = z * 64 + w * 8 + i;
        float a0 = sc[0][512 + n], a1 = sc[1][512 + n], a2 = sc[2][512 + n];
        float d[48];
#pragma unroll
        for (int jj = 0; jj < 48; jj++) {
            int m = jj * 32 + lane;
            float dx = sc[0][m] - a0;
            float dy = sc[1][m] - a1;
            float dz = sc[2][m] - a2;
            d[jj] = dx * dx + dy * dy + dz * dz;
        }

        // ---- per-lane sorted top-5 (ascending key) ----
        unsigned long long s0 = ~0ull, s1 = ~0ull, s2 = ~0ull, s3 = ~0ull, s4 = ~0ull;
#pragma unroll
        for (int jj = 0; jj < 48; jj++) {
            unsigned long long kc =
                ((unsigned long long)__float_as_uint(d[jj]) << 32) |
                (unsigned)(jj * 32 + lane);
            bool l0 = kc < s0, l1 = kc < s1, l2 = kc < s2, l3 = kc < s3, l4 = kc < s4;
            s4 = l4 ? (l3 ? s3 : kc) : s4;
            s3 = l3 ? (l2 ? s2 : kc) : s3;
            s2 = l2 ? (l1 ? s1 : kc) : s2;
            s1 = l1 ? (l0 ? s0 : kc) : s1;
            s0 = l0 ? kc : s0;
        }

        // ---- 16-round warp merge of lane heads ----
        int ptr = 0;
        int* orow = g_idx + ((size_t)(b * TQ + t) * NQ + n) * KQ;
#pragma unroll
        for (int it = 0; it < KQ; it++) {
            unsigned long long k = s0;
#pragma unroll
            for (int off = 16; off; off >>= 1) {
                unsigned long long o = __shfl_xor_sync(FULL, k, off);
                if (o < k) k = o;
            }
            if (s0 == k) { s0 = s1; s1 = s2; s2 = s3; s3 = s4; s4 = ~0ull; ptr++; }
            if (lane == 0) {
                int m = (int)(k & 0xffffffffu);
                int jwin = m >> 9, nwin = m & 511;
                int te = t - 1 + jwin;
                te = te < 0 ? 0 : (te > TQ - 1 ? TQ - 1 : te);
                orow[it] = te * NQ + nwin;
            }
        }

        // ---- exact fallback if any lane exhausted its local list ----
        if (__any_sync(FULL, ptr >= 5)) {
            unsigned long long removed = 0ull;
            for (int it = 0; it < KQ; it++) {
                float best = 3.4e38f;
                int bj = 0;
#pragma unroll
                for (int jj = 0; jj < 48; jj++) {
                    bool alive = !(removed & (1ull << jj));
                    if (alive && d[jj] < best) { best = d[jj]; bj = jj; }
                }
                int bm = bj * 32 + lane;
#pragma unroll
                for (int off = 16; off; off >>= 1) {
                    float od = __shfl_xor_sync(FULL, best, off);
                    int   om = __shfl_xor_sync(FULL, bm, off);
                    if (od < best || (od == best && om < bm)) { best = od; bm = om; }
                }
                if ((bm & 31) == lane) removed |= (1ull << (bm >> 5));
                if (lane == 0) {
                    int jwin = bm >> 9, nwin = bm & 511;
                    int te = t - 1 + jwin;
                    te = te < 0 ? 0 : (te > TQ - 1 ? TQ - 1 : te);
                    orow[it] = te * NQ + nwin;
                }
            }
        }
    }
}

// ---------------------------------------------------------------------------
// Uniform tf32 GEMM core: 128x128 block, KC=16, 2-stage cp.async double buffer.
// ---------------------------------------------------------------------------
template<int CIN>
__device__ __forceinline__ void gemm_core(const float* __restrict__ A,
                                          const float* __restrict__ W,
                                          float acc[4][4][4], int tid)
{
    constexpr int KC = 16;
    constexpr int NCH = CIN / KC;
    __shared__ uint32_t As[2][128 * 20];
    __shared__ uint32_t Bs[2][128 * 20];

    const int lane = tid & 31, wid = tid >> 5;
    const int gid = lane >> 2, tig = lane & 3;
    const int mbase = (wid & 1) * 64, nbase = (wid >> 1) * 32;

    const int r0 = tid >> 2, s0 = (tid & 3) * 4;
    const int r1 = (tid + 256) >> 2, s1 = s0;

    {
        cp16(&As[0][r0 * 20 + s0], A + (size_t)r0 * CIN + s0);
        cp16(&As[0][r1 * 20 + s1], A + (size_t)r1 * CIN + s1);
        cp16(&Bs[0][r0 * 20 + s0], W + (size_t)r0 * CIN + s0);
        cp16(&Bs[0][r1 * 20 + s1], W + (size_t)r1 * CIN + s1);
        cp_commit();
    }

#pragma unroll 1
    for (int kc = 0; kc < NCH; kc++) {
        const int st = kc & 1;
        if (kc + 1 < NCH) {
            const int k0g = (kc + 1) * KC;
            cp16(&As[st ^ 1][r0 * 20 + s0], A + (size_t)r0 * CIN + k0g + s0);
            cp16(&As[st ^ 1][r1 * 20 + s1], A + (size_t)r1 * CIN + k0g + s1);
            cp16(&Bs[st ^ 1][r0 * 20 + s0], W + (size_t)r0 * CIN + k0g + s0);
            cp16(&Bs[st ^ 1][r1 * 20 + s1], W + (size_t)r1 * CIN + k0g + s1);
            cp_commit();
            cp_wait<1>();
        } else {
            cp_commit();
            cp_wait<0>();
        }
        __syncthreads();

#pragma unroll
        for (int ks = 0; ks < 2; ks++) {
            const int k0 = ks * 8;
            uint32_t af[4][4], bf[4][2];
#pragma unroll
            for (int mt = 0; mt < 4; mt++) {
                int m = mbase + mt * 16 + gid;
                af[mt][0] = As[st][m * 20 + k0 + tig];
                af[mt][1] = As[st][(m + 8) * 20 + k0 + tig];
                af[mt][2] = As[st][m * 20 + k0 + 4 + tig];
                af[mt][3] = As[st][(m + 8) * 20 + k0 + 4 + tig];
            }
#pragma unroll
            for (int nt = 0; nt < 4; nt++) {
                int n = nbase + nt * 8 + gid;
                bf[nt][0] = Bs[st][n * 20 + k0 + tig];
                bf[nt][1] = Bs[st][n * 20 + k0 + 4 + tig];
            }
#pragma unroll
            for (int mt = 0; mt < 4; mt++)
#pragma unroll
                for (int nt = 0; nt < 4; nt++)
                    mma_tf32(acc[mt][nt], af[mt][0], af[mt][1], af[mt][2], af[mt][3],
                             bf[nt][0], bf[nt][1]);
        }
        __syncthreads();
    }
}

// K2: fused QKV projection. grid (128, 3, B).
__global__ void __launch_bounds__(256) k_gemm_qkv()
{
    int b = blockIdx.z;
    int p0 = blockIdx.x * 128;
    int cq = blockIdx.y;
    const float* W = (cq == 0) ? g_wq : ((cq == 1) ? g_wk : g_wv);

    float acc[4][4][4] = {};
    gemm_core<CQ>(g_xtf + (size_t)(b * PQ + p0) * CQ, W, acc, threadIdx.x);

    const int lane = threadIdx.x & 31, wid = threadIdx.x >> 5;
    const int gid = lane >> 2, tig = lane & 3;
    float* base = g_qkv + (size_t)(b * PQ + p0 + (wid & 1) * 64) * 384 + cq * 128 + (wid >> 1) * 32;
#pragma unroll
    for (int mt = 0; mt < 4; mt++) {
        int r = mt * 16 + gid;
#pragma unroll
        for (int nt = 0; nt < 4; nt++) {
            int c = nt * 8 + tig * 2;
            *(float2*)(base + (size_t)r * 384 + c)       = make_float2(acc[mt][nt][0], acc[mt][nt][1]);
            *(float2*)(base + (size_t)(r + 8) * 384 + c) = make_float2(acc[mt][nt][2], acc[mt][nt][3]);
        }
    }
}

// ---------------------------------------------------------------------------
// K3: attention + residual + BN. Writes h pre-rounded to tf32.
// ---------------------------------------------------------------------------
__global__ void __launch_bounds__(256) k_attn(const float* __restrict__ gamma,
                                              const float* __restrict__ beta,
                                              const float* __restrict__ mean,
                                              const float* __restrict__ var)
{
    __shared__ float s_scale[CQ], s_shift[CQ];
    int tid = threadIdx.x;
    if (tid < CQ) {
        float sc = gamma[tid] * rsqrtf(var[tid] + 1e-5f);
        s_scale[tid] = sc;
        s_shift[tid] = beta[tid] - mean[tid] * sc;
    }
    __syncthreads();

    int lane = tid & 31, w = tid >> 5;
    const float rs = 0.17677669529663687f; // 1/sqrt(32)

    for (int i = 0; i < 8; i++) {
        int g = blockIdx.x * 64 + w * 8 + i;
        int b = g >> 14;
        int bbase = b << 14;

        const float4* qk = (const float4*)(g_qkv + (size_t)g * 384);
        float4 qv = qk[lane];
        float4 ks = qk[32 + lane];
        float4 vs = qk[64 + lane];

        const int* irow = g_idx + (size_t)g * KQ;
        int myidx = irow[lane & 15];

        float dself;
        {
            float p = qv.x * ks.x + qv.y * ks.y + qv.z * ks.z + qv.w * ks.w;
            p += __shfl_xor_sync(0xffffffffu, p, 1);
            p += __shfl_xor_sync(0xffffffffu, p, 2);
            p += __shfl_xor_sync(0xffffffffu, p, 4);
            dself = p;
        }

        float e[16];
#pragma unroll
        for (int k = 0; k < 16; k++) {
            int nb = __shfl_sync(0xffffffffu, myidx, k);
            const float4* kp = (const float4*)(g_qkv + (size_t)(bbase + nb) * 384 + 128);
            float4 kn = kp[lane];
            float p = qv.x * kn.x + qv.y * kn.y + qv.z * kn.z + qv.w * kn.w;
            p += __shfl_xor_sync(0xffffffffu, p, 1);
            p += __shfl_xor_sync(0xffffffffu, p, 2);
            p += __shfl_xor_sync(0xffffffffu, p, 4);
            e[k] = (dself - p) * rs;
        }

        float mx = e[0];
#pragma unroll
        for (int k = 1; k < 16; k++) mx = fmaxf(mx, e[k]);
        float s = 0.f;
#pragma unroll
        for (int k = 0; k < 16; k++) { e[k] = expf(e[k] - mx); s += e[k]; }
        float inv = 1.0f / s;

        float4 acc = vs;
#pragma unroll
        for (int k = 0; k < 16; k++) {
            int nb = __shfl_sync(0xffffffffu, myidx, k);
            const float4* vp = (const float4*)(g_qkv + (size_t)(bbase + nb) * 384 + 256);
            float4 vn = vp[lane];
            float a = e[k] * inv;
            acc.x -= a * vn.x; acc.y -= a * vn.y;
            acc.z -= a * vn.z; acc.w -= a * vn.w;
        }

        const float4* xp = (const float4*)(g_xpm + (size_t)g * CQ);
        float4 xv = xp[lane];
        int c = lane * 4;
        float4 hv;
        hv.x = f2tff((xv.x + acc.x) * s_scale[c + 0] + s_shift[c + 0]);
        hv.y = f2tff((xv.y + acc.y) * s_scale[c + 1] + s_shift[c + 1]);
        hv.z = f2tff((xv.z + acc.z) * s_scale[c + 2] + s_shift[c + 2]);
        hv.w = f2tff((xv.w + acc.w) * s_scale[c + 3] + s_shift[c + 3]);
        ((float4*)(g_h + (size_t)g * CQ))[lane] = hv;
    }
}

// K4: hid = leaky_relu(W1 @ h), tf32-rounded. grid (128, 4, B).
__global__ void __launch_bounds__(256) k_gemm_w1()
{
    int p0g = blockIdx.z * PQ + blockIdx.x * 128;
    int co0 = blockIdx.y * 128;

    float acc[4][4][4] = {};
    gemm_core<CQ>(g_h + (size_t)p0g * CQ, g_w1 + (size_t)co0 * CQ, acc, threadIdx.x);

    const int lane = threadIdx.x & 31, wid = threadIdx.x >> 5;
    const int gid = lane >> 2, tig = lane & 3;
    float* base = g_hid + (size_t)(p0g + (wid & 1) * 64) * HIDQ + co0 + (wid >> 1) * 32;
#pragma unroll
    for (int mt = 0; mt < 4; mt++) {
        int r = mt * 16 + gid;
#pragma unroll
        for (int nt = 0; nt < 4; nt++) {
            int c = nt * 8 + tig * 2;
            float v0 = acc[mt][nt][0], v1 = acc[mt][nt][1];
            float v2 = acc[mt][nt][2], v3 = acc[mt][nt][3];
            v0 = f2tff(v0 > 0.f ? v0 : 0.2f * v0);
            v1 = f2tff(v1 > 0.f ? v1 : 0.2f * v1);
            v2 = f2tff(v2 > 0.f ? v2 : 0.2f * v2);
            v3 = f2tff(v3 > 0.f ? v3 : 0.2f * v3);
            *(float2*)(base + (size_t)r * HIDQ + c)       = make_float2(v0, v1);
            *(float2*)(base + (size_t)(r + 8) * HIDQ + c) = make_float2(v2, v3);
        }
    }
}

// K5: y = W2 @ hid, channel-major into d_out at channel offset 4. grid (128,1,B).
__global__ void __launch_bounds__(256) k_gemm_w2(float* __restrict__ out)
{
    int b = blockIdx.z;
    int p0 = blockIdx.x * 128;

    float acc[4][4][4] = {};
    gemm_core<HIDQ>(g_hid + (size_t)(b * PQ + p0) * HIDQ, g_w2, acc, threadIdx.x);

    const int lane = threadIdx.x & 31, wid = threadIdx.x >> 5;
    const int gid = lane >> 2, tig = lane & 3;
    float* ob = out + (size_t)b * OUTC * PQ + (size_t)4 * PQ;
    int rbase = p0 + (wid & 1) * 64;
    int cbase = (wid >> 1) * 32;
#pragma unroll
    for (int mt = 0; mt < 4; mt++) {
        int r = rbase + mt * 16 + gid;
#pragma unroll
        for (int nt = 0; nt < 4; nt++) {
            int c = cbase + nt * 8 + tig * 2;
            ob[(size_t)c * PQ + r]           = acc[mt][nt][0];
            ob[(size_t)(c + 1) * PQ + r]     = acc[mt][nt][1];
            ob[(size_t)c * PQ + r + 8]       = acc[mt][nt][2];
            ob[(size_t)(c + 1) * PQ + r + 8] = acc[mt][nt][3];
        }
    }
}

// ---------------------------------------------------------------------------
extern "C" void kernel_launch(void* const* d_in, const int* in_sizes, int n_in,
                              void* d_out, int out_size)
{
    const float* x     = (const float*)d_in[0];
    const float* Wq    = (const float*)d_in[1];
    const float* Wk    = (const float*)d_in[2];
    const float* Wv    = (const float*)d_in[3];
    const float* W1    = (const float*)d_in[4];
    const float* W2    = (const float*)d_in[5];
    const float* gamma = (const float*)d_in[6];
    const float* beta  = (const float*)d_in[7];
    const float* mean  = (const float*)d_in[8];
    const float* var   = (const float*)d_in[9];
    float* out = (float*)d_out;

    k_roundw<<<256, 256>>>(Wq, Wk, Wv, W1, W2);
    k_transpose<<<dim3(PQ / 32, CQ / 32, BQ), dim3(32, 8)>>>(x);
    k_topk<<<dim3(TQ, BQ, 8), 256>>>(x);
    k_gemm_qkv<<<dim3(PQ / 128, 3, BQ), 256>>>();
    k_attn<<<dim3((BQ * PQ) / 64, 1, 1), 256>>>(gamma, beta, mean, var);
    k_gemm_w1<<<dim3(PQ / 128, HIDQ / 128, BQ), 256>>>();
    k_gemm_w2<<<dim3(PQ / 128, 1, BQ), 256>>>(out);

    for (int b = 0; b < BQ; b++) {
        cudaMemcpyAsync(out + (size_t)b * OUTC * PQ,
                        x + (size_t)b * CQ * PQ,
                        (size_t)4 * PQ * sizeof(float),
                        cudaMemcpyDeviceToDevice);
    }
}

// round 6
// speedup vs baseline: 1.5803x; 1.0639x over previous
#include <cuda_runtime.h>
#include <math.h>
#include <stdint.h>

// Problem constants
#define BQ 2
#define CQ 128
#define TQ 32
#define NQ 512
#define PQ (TQ * NQ)      // 16384 points per batch
#define KQ 16
#define HIDQ 512
#define OUTC 132
#define THREEN 1536

// ---------------------------------------------------------------------------
// Device scratch (static — no allocations allowed)
// ---------------------------------------------------------------------------
__device__ float g_xpm[BQ * PQ * CQ];      // x transposed to (b,p,c), full precision (residual)
__device__ float g_xtf[BQ * PQ * CQ];      // x transposed, tf32-rounded (QKV GEMM input)
__device__ float g_qkv[BQ * PQ * 384];     // (b, p, [q(128) | kx(128) | vx(128)])
__device__ int   g_idx[BQ * PQ * KQ];      // neighbor composite index t_eff*N + n'
__device__ float g_h[BQ * PQ * CQ];        // post-attn+BN h, tf32-rounded (W1 input)
__device__ float g_hid[BQ * PQ * HIDQ];    // leaky(W1@h), tf32-rounded (W2 input)
__device__ float g_wq[CQ * CQ], g_wk[CQ * CQ], g_wv[CQ * CQ];   // rounded weights
__device__ float g_w1[HIDQ * CQ], g_w2[CQ * HIDQ];

// ---------------------------------------------------------------------------
// tf32 / async helpers
// ---------------------------------------------------------------------------
__device__ __forceinline__ uint32_t f2tf(float f)
{
    uint32_t r;
    asm("cvt.rna.tf32.f32 %0, %1;" : "=r"(r) : "f"(f));
    return r;
}
__device__ __forceinline__ float f2tff(float f) { return __uint_as_float(f2tf(f)); }

__device__ __forceinline__ void mma_tf32(float c[4],
                                         uint32_t a0, uint32_t a1, uint32_t a2, uint32_t a3,
                                         uint32_t b0, uint32_t b1)
{
    asm volatile(
        "mma.sync.aligned.m16n8k8.row.col.f32.tf32.tf32.f32 "
        "{%0,%1,%2,%3},{%4,%5,%6,%7},{%8,%9},{%0,%1,%2,%3};"
        : "+f"(c[0]), "+f"(c[1]), "+f"(c[2]), "+f"(c[3])
        : "r"(a0), "r"(a1), "r"(a2), "r"(a3), "r"(b0), "r"(b1));
}

__device__ __forceinline__ void cp16(uint32_t* dst_smem, const float* src)
{
    uint32_t d = (uint32_t)__cvta_generic_to_shared(dst_smem);
    asm volatile("cp.async.cg.shared.global [%0], [%1], 16;" :: "r"(d), "l"(src));
}
__device__ __forceinline__ void cp_commit() { asm volatile("cp.async.commit_group;" ::: "memory"); }
template<int N>
__device__ __forceinline__ void cp_wait() { asm volatile("cp.async.wait_group %0;" :: "n"(N) : "memory"); }

// ---------------------------------------------------------------------------
// K_pre: round all weights to tf32 once.
// ---------------------------------------------------------------------------
__global__ void k_roundw(const float* __restrict__ Wq, const float* __restrict__ Wk,
                         const float* __restrict__ Wv, const float* __restrict__ W1,
                         const float* __restrict__ W2)
{
    int i = blockIdx.x * 256 + threadIdx.x;   // 0 .. 65535
    if (i < CQ * CQ) {
        g_wq[i] = f2tff(Wq[i]);
        g_wk[i] = f2tff(Wk[i]);
        g_wv[i] = f2tff(Wv[i]);
    }
    g_w1[i] = f2tff(W1[i]);
    g_w2[i] = f2tff(W2[i]);
}

// ---------------------------------------------------------------------------
// K0: transpose x (B,C,P) -> g_xpm (full) and g_xtf (tf32-rounded), (B,P,C)
// ---------------------------------------------------------------------------
__global__ void k_transpose(const float* __restrict__ x)
{
    __shared__ float tile[32][33];
    int b = blockIdx.z;
    int p0 = blockIdx.x * 32;
    int c0 = blockIdx.y * 32;
    const float* xb = x + (size_t)b * CQ * PQ;
    int tx = threadIdx.x, ty = threadIdx.y;
#pragma unroll
    for (int i = 0; i < 32; i += 8)
        tile[ty + i][tx] = xb[(size_t)(c0 + ty + i) * PQ + p0 + tx];
    __syncthreads();
    float* op  = g_xpm + (size_t)b * PQ * CQ;
    float* op2 = g_xtf + (size_t)b * PQ * CQ;
#pragma unroll
    for (int i = 0; i < 32; i += 8) {
        float v = tile[tx][ty + i];
        size_t o = (size_t)(p0 + ty + i) * CQ + c0 + tx;
        op[o]  = v;
        op2[o] = f2tff(v);
    }
}

// ---------------------------------------------------------------------------
// K1: top-K neighbor selection.
//   1) per lane: branchless register-sorted top-4 as (f32 d, int m) pairs —
//      strict < keeps exact (d, m) lexicographic order (m increases per lane)
//   2) 16-round warp merge using exact u64 keys (d_bits<<32 | m)
//   3) exact fallback (masked argmin) if any lane exhausted its 4 slots
//      before the final selection round.
// Bit-exact vs jax.lax.top_k(-d2, 16) incl. tie-breaking.
// ---------------------------------------------------------------------------
__global__ void __launch_bounds__(256) k_topk(const float* __restrict__ x)
{
    int t = blockIdx.x, b = blockIdx.y, z = blockIdx.z;
    __shared__ float sc[3][THREEN];
    const float* xb = x + (size_t)b * CQ * PQ;
    int tid = threadIdx.x;

    for (int i = tid; i < 3 * THREEN; i += 256) {
        int c = i / THREEN, m = i % THREEN;
        int j = m >> 9, nn = m & 511;
        int te = t - 1 + j;
        te = te < 0 ? 0 : (te > TQ - 1 ? TQ - 1 : te);
        sc[c][m] = xb[(size_t)c * PQ + te * NQ + nn];
    }
    __syncthreads();

    const unsigned FULL = 0xffffffffu;
    const float FINF = __int_as_float(0x7f800000);
    int lane = tid & 31, w = tid >> 5;

    for (int i = 0; i < 8; i++) {
        int n = z * 64 + w * 8 + i;
        float a0 = sc[0][512 + n], a1 = sc[1][512 + n], a2 = sc[2][512 + n];
        float d[48];
#pragma unroll
        for (int jj = 0; jj < 48; jj++) {
            int m = jj * 32 + lane;
            float dx = sc[0][m] - a0;
            float dy = sc[1][m] - a1;
            float dz = sc[2][m] - a2;
            d[jj] = dx * dx + dy * dy + dz * dz;
        }

        // ---- per-lane sorted top-4 (f32 d + index), strict < insertion ----
        float e0 = FINF, e1 = FINF, e2 = FINF, e3 = FINF;
        int   q0 = 0,    q1 = 0,    q2 = 0,    q3 = 0;
#pragma unroll
        for (int jj = 0; jj < 48; jj++) {
            float dc = d[jj];
            int   mc = jj * 32 + lane;
            bool l0 = dc < e0, l1 = dc < e1, l2 = dc < e2, l3 = dc < e3;
            e3 = l3 ? (l2 ? e2 : dc) : e3;  q3 = l3 ? (l2 ? q2 : mc) : q3;
            e2 = l2 ? (l1 ? e1 : dc) : e2;  q2 = l2 ? (l1 ? q1 : mc) : q2;
            e1 = l1 ? (l0 ? e0 : dc) : e1;  q1 = l1 ? (l0 ? q0 : mc) : q1;
            e0 = l0 ? dc : e0;              q0 = l0 ? mc : q0;
        }

        // ---- 16-round warp merge of lane heads ----
        int ptr = 0;
        bool bad = false;
        int* orow = g_idx + ((size_t)(b * TQ + t) * NQ + n) * KQ;
#pragma unroll
        for (int it = 0; it < KQ; it++) {
            bad |= __any_sync(FULL, ptr >= 4);   // some lane exhausted before this pick
            unsigned long long mykey =
                ((unsigned long long)__float_as_uint(e0) << 32) | (unsigned)q0;
            unsigned long long k = mykey;
#pragma unroll
            for (int off = 16; off; off >>= 1) {
                unsigned long long o = __shfl_xor_sync(FULL, k, off);
                if (o < k) k = o;
            }
            if (mykey == k) {
                e0 = e1; q0 = q1; e1 = e2; q1 = q2; e2 = e3; q2 = q3;
                e3 = FINF; q3 = 0; ptr++;
            }
            if (lane == 0) {
                int m = (int)(k & 0xffffffffu);
                int jwin = m >> 9, nwin = m & 511;
                int te = t - 1 + jwin;
                te = te < 0 ? 0 : (te > TQ - 1 ? TQ - 1 : te);
                orow[it] = te * NQ + nwin;
            }
        }

        // ---- exact fallback ----
        if (bad) {
            unsigned long long removed = 0ull;
            for (int it = 0; it < KQ; it++) {
                float best = 3.4e38f;
                int bj = 0;
#pragma unroll
                for (int jj = 0; jj < 48; jj++) {
                    bool alive = !(removed & (1ull << jj));
                    if (alive && d[jj] < best) { best = d[jj]; bj = jj; }
                }
                int bm = bj * 32 + lane;
#pragma unroll
                for (int off = 16; off; off >>= 1) {
                    float od = __shfl_xor_sync(FULL, best, off);
                    int   om = __shfl_xor_sync(FULL, bm, off);
                    if (od < best || (od == best && om < bm)) { best = od; bm = om; }
                }
                if ((bm & 31) == lane) removed |= (1ull << (bm >> 5));
                if (lane == 0) {
                    int jwin = bm >> 9, nwin = bm & 511;
                    int te = t - 1 + jwin;
                    te = te < 0 ? 0 : (te > TQ - 1 ? TQ - 1 : te);
                    orow[it] = te * NQ + nwin;
                }
            }
        }
    }
}

// ---------------------------------------------------------------------------
// Streaming tf32 GEMM core (used by W2): 128x128 block, KC=16, double buffer,
// ONE __syncthreads per chunk (prefetch targets the buffer last read at kc-1;
// the top sync orders all warps past that compute).
// ---------------------------------------------------------------------------
template<int CIN>
__device__ __forceinline__ void gemm_core(const float* __restrict__ A,
                                          const float* __restrict__ W,
                                          float acc[4][4][4], int tid)
{
    constexpr int KC = 16;
    constexpr int NCH = CIN / KC;
    __shared__ uint32_t As[2][128 * 20];
    __shared__ uint32_t Bs[2][128 * 20];

    const int lane = tid & 31, wid = tid >> 5;
    const int gid = lane >> 2, tig = lane & 3;
    const int mbase = (wid & 1) * 64, nbase = (wid >> 1) * 32;

    const int r0 = tid >> 2, s0 = (tid & 3) * 4;
    const int r1 = r0 + 64;

    {
        cp16(&As[0][r0 * 20 + s0], A + (size_t)r0 * CIN + s0);
        cp16(&As[0][r1 * 20 + s0], A + (size_t)r1 * CIN + s0);
        cp16(&Bs[0][r0 * 20 + s0], W + (size_t)r0 * CIN + s0);
        cp16(&Bs[0][r1 * 20 + s0], W + (size_t)r1 * CIN + s0);
        cp_commit();
    }

#pragma unroll 1
    for (int kc = 0; kc < NCH; kc++) {
        const int st = kc & 1;
        cp_wait<0>();
        __syncthreads();
        if (kc + 1 < NCH) {
            const int k0g = (kc + 1) * KC;
            cp16(&As[st ^ 1][r0 * 20 + s0], A + (size_t)r0 * CIN + k0g + s0);
            cp16(&As[st ^ 1][r1 * 20 + s0], A + (size_t)r1 * CIN + k0g + s0);
            cp16(&Bs[st ^ 1][r0 * 20 + s0], W + (size_t)r0 * CIN + k0g + s0);
            cp16(&Bs[st ^ 1][r1 * 20 + s0], W + (size_t)r1 * CIN + k0g + s0);
            cp_commit();
        }

#pragma unroll
        for (int ks = 0; ks < 2; ks++) {
            const int k0 = ks * 8;
            uint32_t af[4][4], bf[4][2];
#pragma unroll
            for (int mt = 0; mt < 4; mt++) {
                int m = mbase + mt * 16 + gid;
                af[mt][0] = As[st][m * 20 + k0 + tig];
                af[mt][1] = As[st][(m + 8) * 20 + k0 + tig];
                af[mt][2] = As[st][m * 20 + k0 + 4 + tig];
                af[mt][3] = As[st][(m + 8) * 20 + k0 + 4 + tig];
            }
#pragma unroll
            for (int nt = 0; nt < 4; nt++) {
                int n = nbase + nt * 8 + gid;
                bf[nt][0] = Bs[st][n * 20 + k0 + tig];
                bf[nt][1] = Bs[st][n * 20 + k0 + 4 + tig];
            }
#pragma unroll
            for (int mt = 0; mt < 4; mt++)
#pragma unroll
                for (int nt = 0; nt < 4; nt++)
                    mma_tf32(acc[mt][nt], af[mt][0], af[mt][1], af[mt][2], af[mt][3],
                             bf[nt][0], bf[nt][1]);
        }
    }
    __syncthreads();
}

// ---------------------------------------------------------------------------
// A-resident GEMM compute: A tile (128x128 words, pad 132) resident in smem;
// stream one 128x16 B chunk per iteration through a double buffer (pad 20).
// One sync per chunk. k0 indexes A globally, B locally.
// ---------------------------------------------------------------------------
__device__ __forceinline__ void gemm_Ares_pass(const uint32_t* __restrict__ As,
                                               uint32_t* __restrict__ Bs,
                                               const float* __restrict__ W,
                                               float acc[4][4][4],
                                               int tid, bool first)
{
    const int lane = tid & 31, wid = tid >> 5;
    const int gid = lane >> 2, tig = lane & 3;
    const int mbase = (wid & 1) * 64, nbase = (wid >> 1) * 32;
    const int r0 = tid >> 2, s0 = (tid & 3) * 4;
    const int r1 = r0 + 64;

    // prologue: B chunk 0
    cp16(&Bs[r0 * 20 + s0], W + (size_t)r0 * CQ + s0);
    cp16(&Bs[r1 * 20 + s0], W + (size_t)r1 * CQ + s0);
    cp_commit();

#pragma unroll 1
    for (int kc = 0; kc < 8; kc++) {
        const int st = kc & 1;
        cp_wait<0>();
        __syncthreads();
        if (kc + 1 < 8) {
            const int k0g = (kc + 1) * 16;
            uint32_t* Bd = Bs + (st ^ 1) * (128 * 20);
            cp16(&Bd[r0 * 20 + s0], W + (size_t)r0 * CQ + k0g + s0);
            cp16(&Bd[r1 * 20 + s0], W + (size_t)r1 * CQ + k0g + s0);
            cp_commit();
        }
        const uint32_t* Bc = Bs + st * (128 * 20);

#pragma unroll
        for (int ks = 0; ks < 2; ks++) {
            const int ka = kc * 16 + ks * 8;   // A (resident) k index
            const int kb = ks * 8;             // B (buffer) k index
            uint32_t af[4][4], bf[4][2];
#pragma unroll
            for (int mt = 0; mt < 4; mt++) {
                int m = mbase + mt * 16 + gid;
                af[mt][0] = As[m * 132 + ka + tig];
                af[mt][1] = As[(m + 8) * 132 + ka + tig];
                af[mt][2] = As[m * 132 + ka + 4 + tig];
                af[mt][3] = As[(m + 8) * 132 + ka + 4 + tig];
            }
#pragma unroll
            for (int nt = 0; nt < 4; nt++) {
                int n = nbase + nt * 8 + gid;
                bf[nt][0] = Bc[n * 20 + kb + tig];
                bf[nt][1] = Bc[n * 20 + kb + 4 + tig];
            }
#pragma unroll
            for (int mt = 0; mt < 4; mt++)
#pragma unroll
                for (int nt = 0; nt < 4; nt++)
                    mma_tf32(acc[mt][nt], af[mt][0], af[mt][1], af[mt][2], af[mt][3],
                             bf[nt][0], bf[nt][1]);
        }
    }
    (void)first;
}

#define ARES_SMEM ((128 * 132 + 2 * 128 * 20) * 4)   // 88064 B

// K2: merged QKV projection. grid (PQ/128, B). A tile loaded once, 3 weight passes.
__global__ void __launch_bounds__(256) k_gemm_qkv()
{
    extern __shared__ uint32_t sm[];
    uint32_t* As = sm;                    // [128][132]
    uint32_t* Bs = sm + 128 * 132;        // [2][128][20]

    const int b = blockIdx.y;
    const int p0 = blockIdx.x * 128;
    const int tid = threadIdx.x;
    const float* A = g_xtf + (size_t)(b * PQ + p0) * CQ;

    // preload resident A tile (16 cp16 per thread)
#pragma unroll
    for (int it = 0; it < 16; it++) {
        int id = tid + it * 256;
        int r = id >> 5, seg = (id & 31) * 4;
        cp16(&As[r * 132 + seg], A + (size_t)r * CQ + seg);
    }
    cp_commit();

    const int lane = tid & 31, wid = tid >> 5;
    const int gid = lane >> 2, tig = lane & 3;

#pragma unroll 1
    for (int cq = 0; cq < 3; cq++) {
        const float* W = (cq == 0) ? g_wq : ((cq == 1) ? g_wk : g_wv);
        float acc[4][4][4] = {};
        gemm_Ares_pass(As, Bs, W, acc, tid, cq == 0);

        float* base = g_qkv + (size_t)(b * PQ + p0 + (wid & 1) * 64) * 384
                    + cq * 128 + (wid >> 1) * 32;
#pragma unroll
        for (int mt = 0; mt < 4; mt++) {
            int r = mt * 16 + gid;
#pragma unroll
            for (int nt = 0; nt < 4; nt++) {
                int c = nt * 8 + tig * 2;
                *(float2*)(base + (size_t)r * 384 + c)       = make_float2(acc[mt][nt][0], acc[mt][nt][1]);
                *(float2*)(base + (size_t)(r + 8) * 384 + c) = make_float2(acc[mt][nt][2], acc[mt][nt][3]);
            }
        }
    }
}

// K4: W1 with resident h tile. grid (PQ/128, B). 4 output chunks of 128.
__global__ void __launch_bounds__(256) k_gemm_w1()
{
    extern __shared__ uint32_t sm[];
    uint32_t* As = sm;
    uint32_t* Bs = sm + 128 * 132;

    const int b = blockIdx.y;
    const int p0 = blockIdx.x * 128;
    const int tid = threadIdx.x;
    const float* A = g_h + (size_t)(b * PQ + p0) * CQ;

#pragma unroll
    for (int it = 0; it < 16; it++) {
        int id = tid + it * 256;
        int r = id >> 5, seg = (id & 31) * 4;
        cp16(&As[r * 132 + seg], A + (size_t)r * CQ + seg);
    }
    cp_commit();

    const int lane = tid & 31, wid = tid >> 5;
    const int gid = lane >> 2, tig = lane & 3;

#pragma unroll 1
    for (int nt4 = 0; nt4 < 4; nt4++) {
        const int co0 = nt4 * 128;
        float acc[4][4][4] = {};
        gemm_Ares_pass(As, Bs, g_w1 + (size_t)co0 * CQ, acc, tid, nt4 == 0);

        float* base = g_hid + (size_t)(b * PQ + p0 + (wid & 1) * 64) * HIDQ
                    + co0 + (wid >> 1) * 32;
#pragma unroll
        for (int mt = 0; mt < 4; mt++) {
            int r = mt * 16 + gid;
#pragma unroll
            for (int nt = 0; nt < 4; nt++) {
                int c = nt * 8 + tig * 2;
                float v0 = acc[mt][nt][0], v1 = acc[mt][nt][1];
                float v2 = acc[mt][nt][2], v3 = acc[mt][nt][3];
                v0 = f2tff(v0 > 0.f ? v0 : 0.2f * v0);
                v1 = f2tff(v1 > 0.f ? v1 : 0.2f * v1);
                v2 = f2tff(v2 > 0.f ? v2 : 0.2f * v2);
                v3 = f2tff(v3 > 0.f ? v3 : 0.2f * v3);
                *(float2*)(base + (size_t)r * HIDQ + c)       = make_float2(v0, v1);
                *(float2*)(base + (size_t)(r + 8) * HIDQ + c) = make_float2(v2, v3);
            }
        }
    }
}

// ---------------------------------------------------------------------------
// K3: attention + residual + BN. Writes h pre-rounded to tf32. (unchanged)
// ---------------------------------------------------------------------------
__global__ void __launch_bounds__(256) k_attn(const float* __restrict__ gamma,
                                              const float* __restrict__ beta,
                                              const float* __restrict__ mean,
                                              const float* __restrict__ var)
{
    __shared__ float s_scale[CQ], s_shift[CQ];
    int tid = threadIdx.x;
    if (tid < CQ) {
        float sc = gamma[tid] * rsqrtf(var[tid] + 1e-5f);
        s_scale[tid] = sc;
        s_shift[tid] = beta[tid] - mean[tid] * sc;
    }
    __syncthreads();

    int lane = tid & 31, w = tid >> 5;
    const float rs = 0.17677669529663687f; // 1/sqrt(32)

    for (int i = 0; i < 8; i++) {
        int g = blockIdx.x * 64 + w * 8 + i;
        int b = g >> 14;
        int bbase = b << 14;

        const float4* qk = (const float4*)(g_qkv + (size_t)g * 384);
        float4 qv = qk[lane];
        float4 ks = qk[32 + lane];
        float4 vs = qk[64 + lane];

        const int* irow = g_idx + (size_t)g * KQ;
        int myidx = irow[lane & 15];

        float dself;
        {
            float p = qv.x * ks.x + qv.y * ks.y + qv.z * ks.z + qv.w * ks.w;
            p += __shfl_xor_sync(0xffffffffu, p, 1);
            p += __shfl_xor_sync(0xffffffffu, p, 2);
            p += __shfl_xor_sync(0xffffffffu, p, 4);
            dself = p;
        }

        float e[16];
#pragma unroll
        for (int k = 0; k < 16; k++) {
            int nb = __shfl_sync(0xffffffffu, myidx, k);
            const float4* kp = (const float4*)(g_qkv + (size_t)(bbase + nb) * 384 + 128);
            float4 kn = kp[lane];
            float p = qv.x * kn.x + qv.y * kn.y + qv.z * kn.z + qv.w * kn.w;
            p += __shfl_xor_sync(0xffffffffu, p, 1);
            p += __shfl_xor_sync(0xffffffffu, p, 2);
            p += __shfl_xor_sync(0xffffffffu, p, 4);
            e[k] = (dself - p) * rs;
        }

        float mx = e[0];
#pragma unroll
        for (int k = 1; k < 16; k++) mx = fmaxf(mx, e[k]);
        float s = 0.f;
#pragma unroll
        for (int k = 0; k < 16; k++) { e[k] = expf(e[k] - mx); s += e[k]; }
        float inv = 1.0f / s;

        float4 acc = vs;
#pragma unroll
        for (int k = 0; k < 16; k++) {
            int nb = __shfl_sync(0xffffffffu, myidx, k);
            const float4* vp = (const float4*)(g_qkv + (size_t)(bbase + nb) * 384 + 256);
            float4 vn = vp[lane];
            float a = e[k] * inv;
            acc.x -= a * vn.x; acc.y -= a * vn.y;
            acc.z -= a * vn.z; acc.w -= a * vn.w;
        }

        const float4* xp = (const float4*)(g_xpm + (size_t)g * CQ);
        float4 xv = xp[lane];
        int c = lane * 4;
        float4 hv;
        hv.x = f2tff((xv.x + acc.x) * s_scale[c + 0] + s_shift[c + 0]);
        hv.y = f2tff((xv.y + acc.y) * s_scale[c + 1] + s_shift[c + 1]);
        hv.z = f2tff((xv.z + acc.z) * s_scale[c + 2] + s_shift[c + 2]);
        hv.w = f2tff((xv.w + acc.w) * s_scale[c + 3] + s_shift[c + 3]);
        ((float4*)(g_h + (size_t)g * CQ))[lane] = hv;
    }
}

// K5: y = W2 @ hid, channel-major into d_out at channel offset 4. grid (128,1,B).
__global__ void __launch_bounds__(256) k_gemm_w2(float* __restrict__ out)
{
    int b = blockIdx.z;
    int p0 = blockIdx.x * 128;

    float acc[4][4][4] = {};
    gemm_core<HIDQ>(g_hid + (size_t)(b * PQ + p0) * HIDQ, g_w2, acc, threadIdx.x);

    const int lane = threadIdx.x & 31, wid = threadIdx.x >> 5;
    const int gid = lane >> 2, tig = lane & 3;
    float* ob = out + (size_t)b * OUTC * PQ + (size_t)4 * PQ;
    int rbase = p0 + (wid & 1) * 64;
    int cbase = (wid >> 1) * 32;
#pragma unroll
    for (int mt = 0; mt < 4; mt++) {
        int r = rbase + mt * 16 + gid;
#pragma unroll
        for (int nt = 0; nt < 4; nt++) {
            int c = cbase + nt * 8 + tig * 2;
            ob[(size_t)c * PQ + r]           = acc[mt][nt][0];
            ob[(size_t)(c + 1) * PQ + r]     = acc[mt][nt][1];
            ob[(size_t)c * PQ + r + 8]       = acc[mt][nt][2];
            ob[(size_t)(c + 1) * PQ + r + 8] = acc[mt][nt][3];
        }
    }
}

// ---------------------------------------------------------------------------
extern "C" void kernel_launch(void* const* d_in, const int* in_sizes, int n_in,
                              void* d_out, int out_size)
{
    const float* x     = (const float*)d_in[0];
    const float* Wq    = (const float*)d_in[1];
    const float* Wk    = (const float*)d_in[2];
    const float* Wv    = (const float*)d_in[3];
    const float* W1    = (const float*)d_in[4];
    const float* W2    = (const float*)d_in[5];
    const float* gamma = (const float*)d_in[6];
    const float* beta  = (const float*)d_in[7];
    const float* mean  = (const float*)d_in[8];
    const float* var   = (const float*)d_in[9];
    float* out = (float*)d_out;

    static int smem_set = 0;
    if (!smem_set) {
        cudaFuncSetAttribute(k_gemm_qkv, cudaFuncAttributeMaxDynamicSharedMemorySize, ARES_SMEM);
        cudaFuncSetAttribute(k_gemm_w1,  cudaFuncAttributeMaxDynamicSharedMemorySize, ARES_SMEM);
        smem_set = 1;
    }

    k_roundw<<<256, 256>>>(Wq, Wk, Wv, W1, W2);
    k_transpose<<<dim3(PQ / 32, CQ / 32, BQ), dim3(32, 8)>>>(x);
    k_topk<<<dim3(TQ, BQ, 8), 256>>>(x);
    k_gemm_qkv<<<dim3(PQ / 128, BQ), 256, ARES_SMEM>>>();
    k_attn<<<dim3((BQ * PQ) / 64, 1, 1), 256>>>(gamma, beta, mean, var);
    k_gemm_w1<<<dim3(PQ / 128, BQ), 256, ARES_SMEM>>>();
    k_gemm_w2<<<dim3(PQ / 128, 1, BQ), 256>>>(out);

    for (int b = 0; b < BQ; b++) {
        cudaMemcpyAsync(out + (size_t)b * OUTC * PQ,
                        x + (size_t)b * CQ * PQ,
                        (size_t)4 * PQ * sizeof(float),
                        cudaMemcpyDeviceToDevice);
    }
}

// round 7
// speedup vs baseline: 1.6104x; 1.0191x over previous
#include <cuda_runtime.h>
#include <math.h>
#include <stdint.h>

// Problem constants
#define BQ 2
#define CQ 128
#define TQ 32
#define NQ 512
#define PQ (TQ * NQ)      // 16384 points per batch
#define KQ 16
#define HIDQ 512
#define OUTC 132
#define THREEN 1536

// ---------------------------------------------------------------------------
// Device scratch (static — no allocations allowed)
// ---------------------------------------------------------------------------
__device__ float g_xpm[BQ * PQ * CQ];      // x transposed to (b,p,c), full precision (residual)
__device__ float g_xtf[BQ * PQ * CQ];      // x transposed, tf32-rounded (QKV GEMM input)
__device__ float g_qkv[BQ * PQ * 384];     // (b, p, [q(128) | kx(128) | vx(128)])
__device__ int   g_idx[BQ * PQ * KQ];      // neighbor composite index t_eff*N + n'
__device__ float g_h[BQ * PQ * CQ];        // post-attn+BN h, tf32-rounded (W1 input)
__device__ float g_hid[BQ * PQ * HIDQ];    // leaky(W1@h), tf32-rounded (W2 input)
__device__ float g_wq[CQ * CQ], g_wk[CQ * CQ], g_wv[CQ * CQ];   // rounded weights
__device__ float g_w1[HIDQ * CQ], g_w2[CQ * HIDQ];

// ---------------------------------------------------------------------------
// tf32 / async helpers
// ---------------------------------------------------------------------------
__device__ __forceinline__ uint32_t f2tf(float f)
{
    uint32_t r;
    asm("cvt.rna.tf32.f32 %0, %1;" : "=r"(r) : "f"(f));
    return r;
}
__device__ __forceinline__ float f2tff(float f) { return __uint_as_float(f2tf(f)); }

__device__ __forceinline__ void mma_tf32(float c[4],
                                         uint32_t a0, uint32_t a1, uint32_t a2, uint32_t a3,
                                         uint32_t b0, uint32_t b1)
{
    asm volatile(
        "mma.sync.aligned.m16n8k8.row.col.f32.tf32.tf32.f32 "
        "{%0,%1,%2,%3},{%4,%5,%6,%7},{%8,%9},{%0,%1,%2,%3};"
        : "+f"(c[0]), "+f"(c[1]), "+f"(c[2]), "+f"(c[3])
        : "r"(a0), "r"(a1), "r"(a2), "r"(a3), "r"(b0), "r"(b1));
}

__device__ __forceinline__ void cp16(uint32_t* dst_smem, const float* src)
{
    uint32_t d = (uint32_t)__cvta_generic_to_shared(dst_smem);
    asm volatile("cp.async.cg.shared.global [%0], [%1], 16;" :: "r"(d), "l"(src));
}
__device__ __forceinline__ void cp_commit() { asm volatile("cp.async.commit_group;" ::: "memory"); }
template<int N>
__device__ __forceinline__ void cp_wait() { asm volatile("cp.async.wait_group %0;" :: "n"(N) : "memory"); }

// ---------------------------------------------------------------------------
// K_pre: round all weights to tf32 once.
// ---------------------------------------------------------------------------
__global__ void k_roundw(const float* __restrict__ Wq, const float* __restrict__ Wk,
                         const float* __restrict__ Wv, const float* __restrict__ W1,
                         const float* __restrict__ W2)
{
    int i = blockIdx.x * 256 + threadIdx.x;   // 0 .. 65535
    if (i < CQ * CQ) {
        g_wq[i] = f2tff(Wq[i]);
        g_wk[i] = f2tff(Wk[i]);
        g_wv[i] = f2tff(Wv[i]);
    }
    g_w1[i] = f2tff(W1[i]);
    g_w2[i] = f2tff(W2[i]);
}

// ---------------------------------------------------------------------------
// K0: transpose x (B,C,P) -> g_xpm (full) and g_xtf (tf32-rounded), (B,P,C).
// Also writes out channels 0..3 (= x channels 0..3) directly, replacing the
// two D2D memcpy graph nodes.
// ---------------------------------------------------------------------------
__global__ void k_transpose(const float* __restrict__ x, float* __restrict__ out)
{
    __shared__ float tile[32][33];
    int b = blockIdx.z;
    int p0 = blockIdx.x * 32;
    int c0 = blockIdx.y * 32;
    const float* xb = x + (size_t)b * CQ * PQ;
    int tx = threadIdx.x, ty = threadIdx.y;
#pragma unroll
    for (int i = 0; i < 32; i += 8) {
        float v = xb[(size_t)(c0 + ty + i) * PQ + p0 + tx];
        tile[ty + i][tx] = v;
        if (c0 == 0 && (ty + i) < 4)
            out[(size_t)b * OUTC * PQ + (size_t)(ty + i) * PQ + p0 + tx] = v;
    }
    __syncthreads();
    float* op  = g_xpm + (size_t)b * PQ * CQ;
    float* op2 = g_xtf + (size_t)b * PQ * CQ;
#pragma unroll
    for (int i = 0; i < 32; i += 8) {
        float v = tile[tx][ty + i];
        size_t o = (size_t)(p0 + ty + i) * CQ + c0 + tx;
        op[o]  = v;
        op2[o] = f2tff(v);
    }
}

// ---------------------------------------------------------------------------
// K1: top-K neighbor selection.
//   1) per lane: fused distance-compute + branchless sorted top-4 insertion
//      (no d[] array -> low registers, high occupancy). Exact (a-b)^2 sums,
//      strict < insertion keeps exact (d, m) lexicographic order.
//   2) 16-round warp merge using exact u64 keys (d_bits<<32 | m)
//   3) exact fallback (masked argmin, distances recomputed) if any lane
//      exhausted its 4 slots before the final selection round.
// Bit-exact vs jax.lax.top_k(-d2, 16) incl. tie-breaking.
// ---------------------------------------------------------------------------
__global__ void __launch_bounds__(256) k_topk(const float* __restrict__ x)
{
    int t = blockIdx.x, b = blockIdx.y, z = blockIdx.z;
    __shared__ float sc[3][THREEN];
    const float* xb = x + (size_t)b * CQ * PQ;
    int tid = threadIdx.x;

    for (int i = tid; i < 3 * THREEN; i += 256) {
        int c = i / THREEN, m = i % THREEN;
        int j = m >> 9, nn = m & 511;
        int te = t - 1 + j;
        te = te < 0 ? 0 : (te > TQ - 1 ? TQ - 1 : te);
        sc[c][m] = xb[(size_t)c * PQ + te * NQ + nn];
    }
    __syncthreads();

    const unsigned FULL = 0xffffffffu;
    const float FINF = __int_as_float(0x7f800000);
    int lane = tid & 31, w = tid >> 5;

    for (int i = 0; i < 8; i++) {
        int n = z * 64 + w * 8 + i;
        float a0 = sc[0][512 + n], a1 = sc[1][512 + n], a2 = sc[2][512 + n];

        // ---- fused distance + sorted top-4 insertion ----
        float e0 = FINF, e1 = FINF, e2 = FINF, e3 = FINF;
        int   q0 = 0,    q1 = 0,    q2 = 0,    q3 = 0;
#pragma unroll
        for (int jj = 0; jj < 48; jj++) {
            int m = jj * 32 + lane;
            float dx = sc[0][m] - a0;
            float dy = sc[1][m] - a1;
            float dz = sc[2][m] - a2;
            float dc = dx * dx + dy * dy + dz * dz;
            bool l0 = dc < e0, l1 = dc < e1, l2 = dc < e2, l3 = dc < e3;
            e3 = l3 ? (l2 ? e2 : dc) : e3;  q3 = l3 ? (l2 ? q2 : m) : q3;
            e2 = l2 ? (l1 ? e1 : dc) : e2;  q2 = l2 ? (l1 ? q1 : m) : q2;
            e1 = l1 ? (l0 ? e0 : dc) : e1;  q1 = l1 ? (l0 ? q0 : m) : q1;
            e0 = l0 ? dc : e0;              q0 = l0 ? m : q0;
        }

        // ---- 16-round warp merge of lane heads ----
        int ptr = 0;
        bool bad = false;
        int* orow = g_idx + ((size_t)(b * TQ + t) * NQ + n) * KQ;
#pragma unroll
        for (int it = 0; it < KQ; it++) {
            bad |= __any_sync(FULL, ptr >= 4);
            unsigned long long mykey =
                ((unsigned long long)__float_as_uint(e0) << 32) | (unsigned)q0;
            unsigned long long k = mykey;
#pragma unroll
            for (int off = 16; off; off >>= 1) {
                unsigned long long o = __shfl_xor_sync(FULL, k, off);
                if (o < k) k = o;
            }
            if (mykey == k) {
                e0 = e1; q0 = q1; e1 = e2; q1 = q2; e2 = e3; q2 = q3;
                e3 = FINF; q3 = 0; ptr++;
            }
            if (lane == 0) {
                int m = (int)(k & 0xffffffffu);
                int jwin = m >> 9, nwin = m & 511;
                int te = t - 1 + jwin;
                te = te < 0 ? 0 : (te > TQ - 1 ? TQ - 1 : te);
                orow[it] = te * NQ + nwin;
            }
        }

        // ---- exact fallback (distances recomputed; rare) ----
        if (bad) {
            unsigned long long removed = 0ull;
            for (int it = 0; it < KQ; it++) {
                float best = 3.4e38f;
                int bj = 0;
#pragma unroll
                for (int jj = 0; jj < 48; jj++) {
                    int m = jj * 32 + lane;
                    float dx = sc[0][m] - a0;
                    float dy = sc[1][m] - a1;
                    float dz = sc[2][m] - a2;
                    float dc = dx * dx + dy * dy + dz * dz;
                    bool alive = !(removed & (1ull << jj));
                    if (alive && dc < best) { best = dc; bj = jj; }
                }
                int bm = bj * 32 + lane;
#pragma unroll
                for (int off = 16; off; off >>= 1) {
                    float od = __shfl_xor_sync(FULL, best, off);
                    int   om = __shfl_xor_sync(FULL, bm, off);
                    if (od < best || (od == best && om < bm)) { best = od; bm = om; }
                }
                if ((bm & 31) == lane) removed |= (1ull << (bm >> 5));
                if (lane == 0) {
                    int jwin = bm >> 9, nwin = bm & 511;
                    int te = t - 1 + jwin;
                    te = te < 0 ? 0 : (te > TQ - 1 ? TQ - 1 : te);
                    orow[it] = te * NQ + nwin;
                }
            }
        }
    }
}

// ---------------------------------------------------------------------------
// Streaming tf32 GEMM core (used by W2): 128x128 block, KC=16, double buffer,
// one __syncthreads per chunk.
// ---------------------------------------------------------------------------
template<int CIN>
__device__ __forceinline__ void gemm_core(const float* __restrict__ A,
                                          const float* __restrict__ W,
                                          float acc[4][4][4], int tid)
{
    constexpr int KC = 16;
    constexpr int NCH = CIN / KC;
    __shared__ uint32_t As[2][128 * 20];
    __shared__ uint32_t Bs[2][128 * 20];

    const int lane = tid & 31, wid = tid >> 5;
    const int gid = lane >> 2, tig = lane & 3;
    const int mbase = (wid & 1) * 64, nbase = (wid >> 1) * 32;

    const int r0 = tid >> 2, s0 = (tid & 3) * 4;
    const int r1 = r0 + 64;

    {
        cp16(&As[0][r0 * 20 + s0], A + (size_t)r0 * CIN + s0);
        cp16(&As[0][r1 * 20 + s0], A + (size_t)r1 * CIN + s0);
        cp16(&Bs[0][r0 * 20 + s0], W + (size_t)r0 * CIN + s0);
        cp16(&Bs[0][r1 * 20 + s0], W + (size_t)r1 * CIN + s0);
        cp_commit();
    }

#pragma unroll 1
    for (int kc = 0; kc < NCH; kc++) {
        const int st = kc & 1;
        cp_wait<0>();
        __syncthreads();
        if (kc + 1 < NCH) {
            const int k0g = (kc + 1) * KC;
            cp16(&As[st ^ 1][r0 * 20 + s0], A + (size_t)r0 * CIN + k0g + s0);
            cp16(&As[st ^ 1][r1 * 20 + s0], A + (size_t)r1 * CIN + k0g + s0);
            cp16(&Bs[st ^ 1][r0 * 20 + s0], W + (size_t)r0 * CIN + k0g + s0);
            cp16(&Bs[st ^ 1][r1 * 20 + s0], W + (size_t)r1 * CIN + k0g + s0);
            cp_commit();
        }

#pragma unroll
        for (int ks = 0; ks < 2; ks++) {
            const int k0 = ks * 8;
            uint32_t af[4][4], bf[4][2];
#pragma unroll
            for (int mt = 0; mt < 4; mt++) {
                int m = mbase + mt * 16 + gid;
                af[mt][0] = As[st][m * 20 + k0 + tig];
                af[mt][1] = As[st][(m + 8) * 20 + k0 + tig];
                af[mt][2] = As[st][m * 20 + k0 + 4 + tig];
                af[mt][3] = As[st][(m + 8) * 20 + k0 + 4 + tig];
            }
#pragma unroll
            for (int nt = 0; nt < 4; nt++) {
                int n = nbase + nt * 8 + gid;
                bf[nt][0] = Bs[st][n * 20 + k0 + tig];
                bf[nt][1] = Bs[st][n * 20 + k0 + 4 + tig];
            }
#pragma unroll
            for (int mt = 0; mt < 4; mt++)
#pragma unroll
                for (int nt = 0; nt < 4; nt++)
                    mma_tf32(acc[mt][nt], af[mt][0], af[mt][1], af[mt][2], af[mt][3],
                             bf[nt][0], bf[nt][1]);
        }
    }
    __syncthreads();
}

// ---------------------------------------------------------------------------
// A-resident GEMM compute (unchanged from round 6).
// ---------------------------------------------------------------------------
__device__ __forceinline__ void gemm_Ares_pass(const uint32_t* __restrict__ As,
                                               uint32_t* __restrict__ Bs,
                                               const float* __restrict__ W,
                                               float acc[4][4][4],
                                               int tid, bool first)
{
    const int lane = tid & 31, wid = tid >> 5;
    const int gid = lane >> 2, tig = lane & 3;
    const int mbase = (wid & 1) * 64, nbase = (wid >> 1) * 32;
    const int r0 = tid >> 2, s0 = (tid & 3) * 4;
    const int r1 = r0 + 64;

    cp16(&Bs[r0 * 20 + s0], W + (size_t)r0 * CQ + s0);
    cp16(&Bs[r1 * 20 + s0], W + (size_t)r1 * CQ + s0);
    cp_commit();

#pragma unroll 1
    for (int kc = 0; kc < 8; kc++) {
        const int st = kc & 1;
        cp_wait<0>();
        __syncthreads();
        if (kc + 1 < 8) {
            const int k0g = (kc + 1) * 16;
            uint32_t* Bd = Bs + (st ^ 1) * (128 * 20);
            cp16(&Bd[r0 * 20 + s0], W + (size_t)r0 * CQ + k0g + s0);
            cp16(&Bd[r1 * 20 + s0], W + (size_t)r1 * CQ + k0g + s0);
            cp_commit();
        }
        const uint32_t* Bc = Bs + st * (128 * 20);

#pragma unroll
        for (int ks = 0; ks < 2; ks++) {
            const int ka = kc * 16 + ks * 8;
            const int kb = ks * 8;
            uint32_t af[4][4], bf[4][2];
#pragma unroll
            for (int mt = 0; mt < 4; mt++) {
                int m = mbase + mt * 16 + gid;
                af[mt][0] = As[m * 132 + ka + tig];
                af[mt][1] = As[(m + 8) * 132 + ka + tig];
                af[mt][2] = As[m * 132 + ka + 4 + tig];
                af[mt][3] = As[(m + 8) * 132 + ka + 4 + tig];
            }
#pragma unroll
            for (int nt = 0; nt < 4; nt++) {
                int n = nbase + nt * 8 + gid;
                bf[nt][0] = Bc[n * 20 + kb + tig];
                bf[nt][1] = Bc[n * 20 + kb + 4 + tig];
            }
#pragma unroll
            for (int mt = 0; mt < 4; mt++)
#pragma unroll
                for (int nt = 0; nt < 4; nt++)
                    mma_tf32(acc[mt][nt], af[mt][0], af[mt][1], af[mt][2], af[mt][3],
                             bf[nt][0], bf[nt][1]);
        }
    }
    (void)first;
}

#define ARES_SMEM ((128 * 132 + 2 * 128 * 20) * 4)   // 88064 B

// K2: merged QKV projection. grid (PQ/128, B). A tile loaded once, 3 weight passes.
__global__ void __launch_bounds__(256) k_gemm_qkv()
{
    extern __shared__ uint32_t sm[];
    uint32_t* As = sm;                    // [128][132]
    uint32_t* Bs = sm + 128 * 132;        // [2][128][20]

    const int b = blockIdx.y;
    const int p0 = blockIdx.x * 128;
    const int tid = threadIdx.x;
    const float* A = g_xtf + (size_t)(b * PQ + p0) * CQ;

#pragma unroll
    for (int it = 0; it < 16; it++) {
        int id = tid + it * 256;
        int r = id >> 5, seg = (id & 31) * 4;
        cp16(&As[r * 132 + seg], A + (size_t)r * CQ + seg);
    }
    cp_commit();

    const int lane = tid & 31, wid = tid >> 5;
    const int gid = lane >> 2, tig = lane & 3;

#pragma unroll 1
    for (int cq = 0; cq < 3; cq++) {
        const float* W = (cq == 0) ? g_wq : ((cq == 1) ? g_wk : g_wv);
        float acc[4][4][4] = {};
        gemm_Ares_pass(As, Bs, W, acc, tid, cq == 0);

        float* base = g_qkv + (size_t)(b * PQ + p0 + (wid & 1) * 64) * 384
                    + cq * 128 + (wid >> 1) * 32;
#pragma unroll
        for (int mt = 0; mt < 4; mt++) {
            int r = mt * 16 + gid;
#pragma unroll
            for (int nt = 0; nt < 4; nt++) {
                int c = nt * 8 + tig * 2;
                *(float2*)(base + (size_t)r * 384 + c)       = make_float2(acc[mt][nt][0], acc[mt][nt][1]);
                *(float2*)(base + (size_t)(r + 8) * 384 + c) = make_float2(acc[mt][nt][2], acc[mt][nt][3]);
            }
        }
    }
}

// K4: W1 with resident h tile. grid (PQ/128, B). 4 output chunks of 128.
__global__ void __launch_bounds__(256) k_gemm_w1()
{
    extern __shared__ uint32_t sm[];
    uint32_t* As = sm;
    uint32_t* Bs = sm + 128 * 132;

    const int b = blockIdx.y;
    const int p0 = blockIdx.x * 128;
    const int tid = threadIdx.x;
    const float* A = g_h + (size_t)(b * PQ + p0) * CQ;

#pragma unroll
    for (int it = 0; it < 16; it++) {
        int id = tid + it * 256;
        int r = id >> 5, seg = (id & 31) * 4;
        cp16(&As[r * 132 + seg], A + (size_t)r * CQ + seg);
    }
    cp_commit();

    const int lane = tid & 31, wid = tid >> 5;
    const int gid = lane >> 2, tig = lane & 3;

#pragma unroll 1
    for (int nt4 = 0; nt4 < 4; nt4++) {
        const int co0 = nt4 * 128;
        float acc[4][4][4] = {};
        gemm_Ares_pass(As, Bs, g_w1 + (size_t)co0 * CQ, acc, tid, nt4 == 0);

        float* base = g_hid + (size_t)(b * PQ + p0 + (wid & 1) * 64) * HIDQ
                    + co0 + (wid >> 1) * 32;
#pragma unroll
        for (int mt = 0; mt < 4; mt++) {
            int r = mt * 16 + gid;
#pragma unroll
            for (int nt = 0; nt < 4; nt++) {
                int c = nt * 8 + tig * 2;
                float v0 = acc[mt][nt][0], v1 = acc[mt][nt][1];
                float v2 = acc[mt][nt][2], v3 = acc[mt][nt][3];
                v0 = f2tff(v0 > 0.f ? v0 : 0.2f * v0);
                v1 = f2tff(v1 > 0.f ? v1 : 0.2f * v1);
                v2 = f2tff(v2 > 0.f ? v2 : 0.2f * v2);
                v3 = f2tff(v3 > 0.f ? v3 : 0.2f * v3);
                *(float2*)(base + (size_t)r * HIDQ + c)       = make_float2(v0, v1);
                *(float2*)(base + (size_t)(r + 8) * HIDQ + c) = make_float2(v2, v3);
            }
        }
    }
}

// ---------------------------------------------------------------------------
// K3: attention + residual + BN. Writes h pre-rounded to tf32. (unchanged)
// ---------------------------------------------------------------------------
__global__ void __launch_bounds__(256) k_attn(const float* __restrict__ gamma,
                                              const float* __restrict__ beta,
                                              const float* __restrict__ mean,
                                              const float* __restrict__ var)
{
    __shared__ float s_scale[CQ], s_shift[CQ];
    int tid = threadIdx.x;
    if (tid < CQ) {
        float sc = gamma[tid] * rsqrtf(var[tid] + 1e-5f);
        s_scale[tid] = sc;
        s_shift[tid] = beta[tid] - mean[tid] * sc;
    }
    __syncthreads();

    int lane = tid & 31, w = tid >> 5;
    const float rs = 0.17677669529663687f; // 1/sqrt(32)

    for (int i = 0; i < 8; i++) {
        int g = blockIdx.x * 64 + w * 8 + i;
        int b = g >> 14;
        int bbase = b << 14;

        const float4* qk = (const float4*)(g_qkv + (size_t)g * 384);
        float4 qv = qk[lane];
        float4 ks = qk[32 + lane];
        float4 vs = qk[64 + lane];

        const int* irow = g_idx + (size_t)g * KQ;
        int myidx = irow[lane & 15];

        float dself;
        {
            float p = qv.x * ks.x + qv.y * ks.y + qv.z * ks.z + qv.w * ks.w;
            p += __shfl_xor_sync(0xffffffffu, p, 1);
            p += __shfl_xor_sync(0xffffffffu, p, 2);
            p += __shfl_xor_sync(0xffffffffu, p, 4);
            dself = p;
        }

        float e[16];
#pragma unroll
        for (int k = 0; k < 16; k++) {
            int nb = __shfl_sync(0xffffffffu, myidx, k);
            const float4* kp = (const float4*)(g_qkv + (size_t)(bbase + nb) * 384 + 128);
            float4 kn = kp[lane];
            float p = qv.x * kn.x + qv.y * kn.y + qv.z * kn.z + qv.w * kn.w;
            p += __shfl_xor_sync(0xffffffffu, p, 1);
            p += __shfl_xor_sync(0xffffffffu, p, 2);
            p += __shfl_xor_sync(0xffffffffu, p, 4);
            e[k] = (dself - p) * rs;
        }

        float mx = e[0];
#pragma unroll
        for (int k = 1; k < 16; k++) mx = fmaxf(mx, e[k]);
        float s = 0.f;
#pragma unroll
        for (int k = 0; k < 16; k++) { e[k] = expf(e[k] - mx); s += e[k]; }
        float inv = 1.0f / s;

        float4 acc = vs;
#pragma unroll
        for (int k = 0; k < 16; k++) {
            int nb = __shfl_sync(0xffffffffu, myidx, k);
            const float4* vp = (const float4*)(g_qkv + (size_t)(bbase + nb) * 384 + 256);
            float4 vn = vp[lane];
            float a = e[k] * inv;
            acc.x -= a * vn.x; acc.y -= a * vn.y;
            acc.z -= a * vn.z; acc.w -= a * vn.w;
        }

        const float4* xp = (const float4*)(g_xpm + (size_t)g * CQ);
        float4 xv = xp[lane];
        int c = lane * 4;
        float4 hv;
        hv.x = f2tff((xv.x + acc.x) * s_scale[c + 0] + s_shift[c + 0]);
        hv.y = f2tff((xv.y + acc.y) * s_scale[c + 1] + s_shift[c + 1]);
        hv.z = f2tff((xv.z + acc.z) * s_scale[c + 2] + s_shift[c + 2]);
        hv.w = f2tff((xv.w + acc.w) * s_scale[c + 3] + s_shift[c + 3]);
        ((float4*)(g_h + (size_t)g * CQ))[lane] = hv;
    }
}

// K5: y = W2 @ hid, channel-major into d_out at channel offset 4. grid (128,1,B).
__global__ void __launch_bounds__(256) k_gemm_w2(float* __restrict__ out)
{
    int b = blockIdx.z;
    int p0 = blockIdx.x * 128;

    float acc[4][4][4] = {};
    gemm_core<HIDQ>(g_hid + (size_t)(b * PQ + p0) * HIDQ, g_w2, acc, threadIdx.x);

    const int lane = threadIdx.x & 31, wid = threadIdx.x >> 5;
    const int gid = lane >> 2, tig = lane & 3;
    float* ob = out + (size_t)b * OUTC * PQ + (size_t)4 * PQ;
    int rbase = p0 + (wid & 1) * 64;
    int cbase = (wid >> 1) * 32;
#pragma unroll
    for (int mt = 0; mt < 4; mt++) {
        int r = rbase + mt * 16 + gid;
#pragma unroll
        for (int nt = 0; nt < 4; nt++) {
            int c = cbase + nt * 8 + tig * 2;
            ob[(size_t)c * PQ + r]           = acc[mt][nt][0];
            ob[(size_t)(c + 1) * PQ + r]     = acc[mt][nt][1];
            ob[(size_t)c * PQ + r + 8]       = acc[mt][nt][2];
            ob[(size_t)(c + 1) * PQ + r + 8] = acc[mt][nt][3];
        }
    }
}

// ---------------------------------------------------------------------------
extern "C" void kernel_launch(void* const* d_in, const int* in_sizes, int n_in,
                              void* d_out, int out_size)
{
    const float* x     = (const float*)d_in[0];
    const float* Wq    = (const float*)d_in[1];
    const float* Wk    = (const float*)d_in[2];
    const float* Wv    = (const float*)d_in[3];
    const float* W1    = (const float*)d_in[4];
    const float* W2    = (const float*)d_in[5];
    const float* gamma = (const float*)d_in[6];
    const float* beta  = (const float*)d_in[7];
    const float* mean  = (const float*)d_in[8];
    const float* var   = (const float*)d_in[9];
    float* out = (float*)d_out;

    static int smem_set = 0;
    if (!smem_set) {
        cudaFuncSetAttribute(k_gemm_qkv, cudaFuncAttributeMaxDynamicSharedMemorySize, ARES_SMEM);
        cudaFuncSetAttribute(k_gemm_w1,  cudaFuncAttributeMaxDynamicSharedMemorySize, ARES_SMEM);
        smem_set = 1;
    }

    k_roundw<<<256, 256>>>(Wq, Wk, Wv, W1, W2);
    k_transpose<<<dim3(PQ / 32, CQ / 32, BQ), dim3(32, 8)>>>(x, out);
    k_topk<<<dim3(TQ, BQ, 8), 256>>>(x);
    k_gemm_qkv<<<dim3(PQ / 128, BQ), 256, ARES_SMEM>>>();
    k_attn<<<dim3((BQ * PQ) / 64, 1, 1), 256>>>(gamma, beta, mean, var);
    k_gemm_w1<<<dim3(PQ / 128, BQ), 256, ARES_SMEM>>>();
    k_gemm_w2<<<dim3(PQ / 128, 1, BQ), 256>>>(out);
}

// round 8
// speedup vs baseline: 1.7846x; 1.1082x over previous
#include <cuda_runtime.h>
#include <math.h>
#include <stdint.h>

// Problem constants
#define BQ 2
#define CQ 128
#define TQ 32
#define NQ 512
#define PQ (TQ * NQ)      // 16384 points per batch
#define KQ 16
#define HIDQ 512
#define OUTC 132
#define THREEN 1536

// ---------------------------------------------------------------------------
// Device scratch (static — no allocations allowed)
// ---------------------------------------------------------------------------
__device__ float g_xpm[BQ * PQ * CQ];      // x transposed to (b,p,c), full precision (residual)
__device__ float g_xtf[BQ * PQ * CQ];      // x transposed, tf32-rounded (QKV GEMM input)
__device__ float g_qkv[BQ * PQ * 384];     // (b, p, [q(128) | kx(128) | vx(128)])
__device__ int   g_idx[BQ * PQ * KQ];      // neighbor composite index t_eff*N + n'
__device__ float g_h[BQ * PQ * CQ];        // post-attn+BN h, tf32-rounded (W1 input)
__device__ float g_hid[BQ * PQ * HIDQ];    // leaky(W1@h), tf32-rounded (W2 input)
__device__ float g_wq[CQ * CQ], g_wk[CQ * CQ], g_wv[CQ * CQ];   // rounded weights
__device__ float g_w1[HIDQ * CQ], g_w2[CQ * HIDQ];

// ---------------------------------------------------------------------------
// tf32 / async helpers
// ---------------------------------------------------------------------------
__device__ __forceinline__ uint32_t f2tf(float f)
{
    uint32_t r;
    asm("cvt.rna.tf32.f32 %0, %1;" : "=r"(r) : "f"(f));
    return r;
}
__device__ __forceinline__ float f2tff(float f) { return __uint_as_float(f2tf(f)); }

__device__ __forceinline__ void mma_tf32(float c[4],
                                         uint32_t a0, uint32_t a1, uint32_t a2, uint32_t a3,
                                         uint32_t b0, uint32_t b1)
{
    asm volatile(
        "mma.sync.aligned.m16n8k8.row.col.f32.tf32.tf32.f32 "
        "{%0,%1,%2,%3},{%4,%5,%6,%7},{%8,%9},{%0,%1,%2,%3};"
        : "+f"(c[0]), "+f"(c[1]), "+f"(c[2]), "+f"(c[3])
        : "r"(a0), "r"(a1), "r"(a2), "r"(a3), "r"(b0), "r"(b1));
}

__device__ __forceinline__ void cp16(uint32_t* dst_smem, const float* src)
{
    uint32_t d = (uint32_t)__cvta_generic_to_shared(dst_smem);
    asm volatile("cp.async.cg.shared.global [%0], [%1], 16;" :: "r"(d), "l"(src));
}
__device__ __forceinline__ void cp_commit() { asm volatile("cp.async.commit_group;" ::: "memory"); }
template<int N>
__device__ __forceinline__ void cp_wait() { asm volatile("cp.async.wait_group %0;" :: "n"(N) : "memory"); }

// ---------------------------------------------------------------------------
// K_pre: round all weights to tf32 once.
// ---------------------------------------------------------------------------
__global__ void k_roundw(const float* __restrict__ Wq, const float* __restrict__ Wk,
                         const float* __restrict__ Wv, const float* __restrict__ W1,
                         const float* __restrict__ W2)
{
    int i = blockIdx.x * 256 + threadIdx.x;   // 0 .. 65535
    if (i < CQ * CQ) {
        g_wq[i] = f2tff(Wq[i]);
        g_wk[i] = f2tff(Wk[i]);
        g_wv[i] = f2tff(Wv[i]);
    }
    g_w1[i] = f2tff(W1[i]);
    g_w2[i] = f2tff(W2[i]);
}

// ---------------------------------------------------------------------------
// K0: transpose x (B,C,P) -> g_xpm (full) and g_xtf (tf32-rounded), (B,P,C).
// Also writes out channels 0..3 (= x channels 0..3) directly.
// ---------------------------------------------------------------------------
__global__ void k_transpose(const float* __restrict__ x, float* __restrict__ out)
{
    __shared__ float tile[32][33];
    int b = blockIdx.z;
    int p0 = blockIdx.x * 32;
    int c0 = blockIdx.y * 32;
    const float* xb = x + (size_t)b * CQ * PQ;
    int tx = threadIdx.x, ty = threadIdx.y;
#pragma unroll
    for (int i = 0; i < 32; i += 8) {
        float v = xb[(size_t)(c0 + ty + i) * PQ + p0 + tx];
        tile[ty + i][tx] = v;
        if (c0 == 0 && (ty + i) < 4)
            out[(size_t)b * OUTC * PQ + (size_t)(ty + i) * PQ + p0 + tx] = v;
    }
    __syncthreads();
    float* op  = g_xpm + (size_t)b * PQ * CQ;
    float* op2 = g_xtf + (size_t)b * PQ * CQ;
#pragma unroll
    for (int i = 0; i < 32; i += 8) {
        float v = tile[tx][ty + i];
        size_t o = (size_t)(p0 + ty + i) * CQ + c0 + tx;
        op[o]  = v;
        op2[o] = f2tff(v);
    }
}

// ---------------------------------------------------------------------------
// K1: top-K neighbor selection (unchanged from round 7 — exact).
// ---------------------------------------------------------------------------
__global__ void __launch_bounds__(256) k_topk(const float* __restrict__ x)
{
    int t = blockIdx.x, b = blockIdx.y, z = blockIdx.z;
    __shared__ float sc[3][THREEN];
    const float* xb = x + (size_t)b * CQ * PQ;
    int tid = threadIdx.x;

    for (int i = tid; i < 3 * THREEN; i += 256) {
        int c = i / THREEN, m = i % THREEN;
        int j = m >> 9, nn = m & 511;
        int te = t - 1 + j;
        te = te < 0 ? 0 : (te > TQ - 1 ? TQ - 1 : te);
        sc[c][m] = xb[(size_t)c * PQ + te * NQ + nn];
    }
    __syncthreads();

    const unsigned FULL = 0xffffffffu;
    const float FINF = __int_as_float(0x7f800000);
    int lane = tid & 31, w = tid >> 5;

    for (int i = 0; i < 8; i++) {
        int n = z * 64 + w * 8 + i;
        float a0 = sc[0][512 + n], a1 = sc[1][512 + n], a2 = sc[2][512 + n];

        float e0 = FINF, e1 = FINF, e2 = FINF, e3 = FINF;
        int   q0 = 0,    q1 = 0,    q2 = 0,    q3 = 0;
#pragma unroll
        for (int jj = 0; jj < 48; jj++) {
            int m = jj * 32 + lane;
            float dx = sc[0][m] - a0;
            float dy = sc[1][m] - a1;
            float dz = sc[2][m] - a2;
            float dc = dx * dx + dy * dy + dz * dz;
            bool l0 = dc < e0, l1 = dc < e1, l2 = dc < e2, l3 = dc < e3;
            e3 = l3 ? (l2 ? e2 : dc) : e3;  q3 = l3 ? (l2 ? q2 : m) : q3;
            e2 = l2 ? (l1 ? e1 : dc) : e2;  q2 = l2 ? (l1 ? q1 : m) : q2;
            e1 = l1 ? (l0 ? e0 : dc) : e1;  q1 = l1 ? (l0 ? q0 : m) : q1;
            e0 = l0 ? dc : e0;              q0 = l0 ? m : q0;
        }

        int ptr = 0;
        bool bad = false;
        int* orow = g_idx + ((size_t)(b * TQ + t) * NQ + n) * KQ;
#pragma unroll
        for (int it = 0; it < KQ; it++) {
            bad |= __any_sync(FULL, ptr >= 4);
            unsigned long long mykey =
                ((unsigned long long)__float_as_uint(e0) << 32) | (unsigned)q0;
            unsigned long long k = mykey;
#pragma unroll
            for (int off = 16; off; off >>= 1) {
                unsigned long long o = __shfl_xor_sync(FULL, k, off);
                if (o < k) k = o;
            }
            if (mykey == k) {
                e0 = e1; q0 = q1; e1 = e2; q1 = q2; e2 = e3; q2 = q3;
                e3 = FINF; q3 = 0; ptr++;
            }
            if (lane == 0) {
                int m = (int)(k & 0xffffffffu);
                int jwin = m >> 9, nwin = m & 511;
                int te = t - 1 + jwin;
                te = te < 0 ? 0 : (te > TQ - 1 ? TQ - 1 : te);
                orow[it] = te * NQ + nwin;
            }
        }

        if (bad) {
            unsigned long long removed = 0ull;
            for (int it = 0; it < KQ; it++) {
                float best = 3.4e38f;
                int bj = 0;
#pragma unroll
                for (int jj = 0; jj < 48; jj++) {
                    int m = jj * 32 + lane;
                    float dx = sc[0][m] - a0;
                    float dy = sc[1][m] - a1;
                    float dz = sc[2][m] - a2;
                    float dc = dx * dx + dy * dy + dz * dz;
                    bool alive = !(removed & (1ull << jj));
                    if (alive && dc < best) { best = dc; bj = jj; }
                }
                int bm = bj * 32 + lane;
#pragma unroll
                for (int off = 16; off; off >>= 1) {
                    float od = __shfl_xor_sync(FULL, best, off);
                    int   om = __shfl_xor_sync(FULL, bm, off);
                    if (od < best || (od == best && om < bm)) { best = od; bm = om; }
                }
                if ((bm & 31) == lane) removed |= (1ull << (bm >> 5));
                if (lane == 0) {
                    int jwin = bm >> 9, nwin = bm & 511;
                    int te = t - 1 + jwin;
                    te = te < 0 ? 0 : (te > TQ - 1 ? TQ - 1 : te);
                    orow[it] = te * NQ + nwin;
                }
            }
        }
    }
}

// ---------------------------------------------------------------------------
// Streaming tf32 GEMM core (used by W2).
// ---------------------------------------------------------------------------
template<int CIN>
__device__ __forceinline__ void gemm_core(const float* __restrict__ A,
                                          const float* __restrict__ W,
                                          float acc[4][4][4], int tid)
{
    constexpr int KC = 16;
    constexpr int NCH = CIN / KC;
    __shared__ uint32_t As[2][128 * 20];
    __shared__ uint32_t Bs[2][128 * 20];

    const int lane = tid & 31, wid = tid >> 5;
    const int gid = lane >> 2, tig = lane & 3;
    const int mbase = (wid & 1) * 64, nbase = (wid >> 1) * 32;

    const int r0 = tid >> 2, s0 = (tid & 3) * 4;
    const int r1 = r0 + 64;

    {
        cp16(&As[0][r0 * 20 + s0], A + (size_t)r0 * CIN + s0);
        cp16(&As[0][r1 * 20 + s0], A + (size_t)r1 * CIN + s0);
        cp16(&Bs[0][r0 * 20 + s0], W + (size_t)r0 * CIN + s0);
        cp16(&Bs[0][r1 * 20 + s0], W + (size_t)r1 * CIN + s0);
        cp_commit();
    }

#pragma unroll 1
    for (int kc = 0; kc < NCH; kc++) {
        const int st = kc & 1;
        cp_wait<0>();
        __syncthreads();
        if (kc + 1 < NCH) {
            const int k0g = (kc + 1) * KC;
            cp16(&As[st ^ 1][r0 * 20 + s0], A + (size_t)r0 * CIN + k0g + s0);
            cp16(&As[st ^ 1][r1 * 20 + s0], A + (size_t)r1 * CIN + k0g + s0);
            cp16(&Bs[st ^ 1][r0 * 20 + s0], W + (size_t)r0 * CIN + k0g + s0);
            cp16(&Bs[st ^ 1][r1 * 20 + s0], W + (size_t)r1 * CIN + k0g + s0);
            cp_commit();
        }

#pragma unroll
        for (int ks = 0; ks < 2; ks++) {
            const int k0 = ks * 8;
            uint32_t af[4][4], bf[4][2];
#pragma unroll
            for (int mt = 0; mt < 4; mt++) {
                int m = mbase + mt * 16 + gid;
                af[mt][0] = As[st][m * 20 + k0 + tig];
                af[mt][1] = As[st][(m + 8) * 20 + k0 + tig];
                af[mt][2] = As[st][m * 20 + k0 + 4 + tig];
                af[mt][3] = As[st][(m + 8) * 20 + k0 + 4 + tig];
            }
#pragma unroll
            for (int nt = 0; nt < 4; nt++) {
                int n = nbase + nt * 8 + gid;
                bf[nt][0] = Bs[st][n * 20 + k0 + tig];
                bf[nt][1] = Bs[st][n * 20 + k0 + 4 + tig];
            }
#pragma unroll
            for (int mt = 0; mt < 4; mt++)
#pragma unroll
                for (int nt = 0; nt < 4; nt++)
                    mma_tf32(acc[mt][nt], af[mt][0], af[mt][1], af[mt][2], af[mt][3],
                             bf[nt][0], bf[nt][1]);
        }
    }
    __syncthreads();
}

// ---------------------------------------------------------------------------
// A-resident GEMM compute (unchanged).
// ---------------------------------------------------------------------------
__device__ __forceinline__ void gemm_Ares_pass(const uint32_t* __restrict__ As,
                                               uint32_t* __restrict__ Bs,
                                               const float* __restrict__ W,
                                               float acc[4][4][4],
                                               int tid, bool first)
{
    const int lane = tid & 31, wid = tid >> 5;
    const int gid = lane >> 2, tig = lane & 3;
    const int mbase = (wid & 1) * 64, nbase = (wid >> 1) * 32;
    const int r0 = tid >> 2, s0 = (tid & 3) * 4;
    const int r1 = r0 + 64;

    cp16(&Bs[r0 * 20 + s0], W + (size_t)r0 * CQ + s0);
    cp16(&Bs[r1 * 20 + s0], W + (size_t)r1 * CQ + s0);
    cp_commit();

#pragma unroll 1
    for (int kc = 0; kc < 8; kc++) {
        const int st = kc & 1;
        cp_wait<0>();
        __syncthreads();
        if (kc + 1 < 8) {
            const int k0g = (kc + 1) * 16;
            uint32_t* Bd = Bs + (st ^ 1) * (128 * 20);
            cp16(&Bd[r0 * 20 + s0], W + (size_t)r0 * CQ + k0g + s0);
            cp16(&Bd[r1 * 20 + s0], W + (size_t)r1 * CQ + k0g + s0);
            cp_commit();
        }
        const uint32_t* Bc = Bs + st * (128 * 20);

#pragma unroll
        for (int ks = 0; ks < 2; ks++) {
            const int ka = kc * 16 + ks * 8;
            const int kb = ks * 8;
            uint32_t af[4][4], bf[4][2];
#pragma unroll
            for (int mt = 0; mt < 4; mt++) {
                int m = mbase + mt * 16 + gid;
                af[mt][0] = As[m * 132 + ka + tig];
                af[mt][1] = As[(m + 8) * 132 + ka + tig];
                af[mt][2] = As[m * 132 + ka + 4 + tig];
                af[mt][3] = As[(m + 8) * 132 + ka + 4 + tig];
            }
#pragma unroll
            for (int nt = 0; nt < 4; nt++) {
                int n = nbase + nt * 8 + gid;
                bf[nt][0] = Bc[n * 20 + kb + tig];
                bf[nt][1] = Bc[n * 20 + kb + 4 + tig];
            }
#pragma unroll
            for (int mt = 0; mt < 4; mt++)
#pragma unroll
                for (int nt = 0; nt < 4; nt++)
                    mma_tf32(acc[mt][nt], af[mt][0], af[mt][1], af[mt][2], af[mt][3],
                             bf[nt][0], bf[nt][1]);
        }
    }
    (void)first;
}

#define ARES_SMEM ((128 * 132 + 2 * 128 * 20) * 4)   // 88064 B

// K2: merged QKV projection. grid (PQ/128, B).
__global__ void __launch_bounds__(256) k_gemm_qkv()
{
    extern __shared__ uint32_t sm[];
    uint32_t* As = sm;                    // [128][132]
    uint32_t* Bs = sm + 128 * 132;        // [2][128][20]

    const int b = blockIdx.y;
    const int p0 = blockIdx.x * 128;
    const int tid = threadIdx.x;
    const float* A = g_xtf + (size_t)(b * PQ + p0) * CQ;

#pragma unroll
    for (int it = 0; it < 16; it++) {
        int id = tid + it * 256;
        int r = id >> 5, seg = (id & 31) * 4;
        cp16(&As[r * 132 + seg], A + (size_t)r * CQ + seg);
    }
    cp_commit();

    const int lane = tid & 31, wid = tid >> 5;
    const int gid = lane >> 2, tig = lane & 3;

#pragma unroll 1
    for (int cq = 0; cq < 3; cq++) {
        const float* W = (cq == 0) ? g_wq : ((cq == 1) ? g_wk : g_wv);
        float acc[4][4][4] = {};
        gemm_Ares_pass(As, Bs, W, acc, tid, cq == 0);

        float* base = g_qkv + (size_t)(b * PQ + p0 + (wid & 1) * 64) * 384
                    + cq * 128 + (wid >> 1) * 32;
#pragma unroll
        for (int mt = 0; mt < 4; mt++) {
            int r = mt * 16 + gid;
#pragma unroll
            for (int nt = 0; nt < 4; nt++) {
                int c = nt * 8 + tig * 2;
                *(float2*)(base + (size_t)r * 384 + c)       = make_float2(acc[mt][nt][0], acc[mt][nt][1]);
                *(float2*)(base + (size_t)(r + 8) * 384 + c) = make_float2(acc[mt][nt][2], acc[mt][nt][3]);
            }
        }
    }
}

// K4: W1 with resident h tile. grid (PQ/128, B).
__global__ void __launch_bounds__(256) k_gemm_w1()
{
    extern __shared__ uint32_t sm[];
    uint32_t* As = sm;
    uint32_t* Bs = sm + 128 * 132;

    const int b = blockIdx.y;
    const int p0 = blockIdx.x * 128;
    const int tid = threadIdx.x;
    const float* A = g_h + (size_t)(b * PQ + p0) * CQ;

#pragma unroll
    for (int it = 0; it < 16; it++) {
        int id = tid + it * 256;
        int r = id >> 5, seg = (id & 31) * 4;
        cp16(&As[r * 132 + seg], A + (size_t)r * CQ + seg);
    }
    cp_commit();

    const int lane = tid & 31, wid = tid >> 5;
    const int gid = lane >> 2, tig = lane & 3;

#pragma unroll 1
    for (int nt4 = 0; nt4 < 4; nt4++) {
        const int co0 = nt4 * 128;
        float acc[4][4][4] = {};
        gemm_Ares_pass(As, Bs, g_w1 + (size_t)co0 * CQ, acc, tid, nt4 == 0);

        float* base = g_hid + (size_t)(b * PQ + p0 + (wid & 1) * 64) * HIDQ
                    + co0 + (wid >> 1) * 32;
#pragma unroll
        for (int mt = 0; mt < 4; mt++) {
            int r = mt * 16 + gid;
#pragma unroll
            for (int nt = 0; nt < 4; nt++) {
                int c = nt * 8 + tig * 2;
                float v0 = acc[mt][nt][0], v1 = acc[mt][nt][1];
                float v2 = acc[mt][nt][2], v3 = acc[mt][nt][3];
                v0 = f2tff(v0 > 0.f ? v0 : 0.2f * v0);
                v1 = f2tff(v1 > 0.f ? v1 : 0.2f * v1);
                v2 = f2tff(v2 > 0.f ? v2 : 0.2f * v2);
                v3 = f2tff(v3 > 0.f ? v3 : 0.2f * v3);
                *(float2*)(base + (size_t)r * HIDQ + c)       = make_float2(v0, v1);
                *(float2*)(base + (size_t)(r + 8) * HIDQ + c) = make_float2(v2, v3);
            }
        }
    }
}

// ---------------------------------------------------------------------------
// K3: attention + residual + BN (unchanged).
// ---------------------------------------------------------------------------
__global__ void __launch_bounds__(256) k_attn(const float* __restrict__ gamma,
                                              const float* __restrict__ beta,
                                              const float* __restrict__ mean,
                                              const float* __restrict__ var)
{
    __shared__ float s_scale[CQ], s_shift[CQ];
    int tid = threadIdx.x;
    if (tid < CQ) {
        float sc = gamma[tid] * rsqrtf(var[tid] + 1e-5f);
        s_scale[tid] = sc;
        s_shift[tid] = beta[tid] - mean[tid] * sc;
    }
    __syncthreads();

    int lane = tid & 31, w = tid >> 5;
    const float rs = 0.17677669529663687f; // 1/sqrt(32)

    for (int i = 0; i < 8; i++) {
        int g = blockIdx.x * 64 + w * 8 + i;
        int b = g >> 14;
        int bbase = b << 14;

        const float4* qk = (const float4*)(g_qkv + (size_t)g * 384);
        float4 qv = qk[lane];
        float4 ks = qk[32 + lane];
        float4 vs = qk[64 + lane];

        const int* irow = g_idx + (size_t)g * KQ;
        int myidx = irow[lane & 15];

        float dself;
        {
            float p = qv.x * ks.x + qv.y * ks.y + qv.z * ks.z + qv.w * ks.w;
            p += __shfl_xor_sync(0xffffffffu, p, 1);
            p += __shfl_xor_sync(0xffffffffu, p, 2);
            p += __shfl_xor_sync(0xffffffffu, p, 4);
            dself = p;
        }

        float e[16];
#pragma unroll
        for (int k = 0; k < 16; k++) {
            int nb = __shfl_sync(0xffffffffu, myidx, k);
            const float4* kp = (const float4*)(g_qkv + (size_t)(bbase + nb) * 384 + 128);
            float4 kn = kp[lane];
            float p = qv.x * kn.x + qv.y * kn.y + qv.z * kn.z + qv.w * kn.w;
            p += __shfl_xor_sync(0xffffffffu, p, 1);
            p += __shfl_xor_sync(0xffffffffu, p, 2);
            p += __shfl_xor_sync(0xffffffffu, p, 4);
            e[k] = (dself - p) * rs;
        }

        float mx = e[0];
#pragma unroll
        for (int k = 1; k < 16; k++) mx = fmaxf(mx, e[k]);
        float s = 0.f;
#pragma unroll
        for (int k = 0; k < 16; k++) { e[k] = expf(e[k] - mx); s += e[k]; }
        float inv = 1.0f / s;

        float4 acc = vs;
#pragma unroll
        for (int k = 0; k < 16; k++) {
            int nb = __shfl_sync(0xffffffffu, myidx, k);
            const float4* vp = (const float4*)(g_qkv + (size_t)(bbase + nb) * 384 + 256);
            float4 vn = vp[lane];
            float a = e[k] * inv;
            acc.x -= a * vn.x; acc.y -= a * vn.y;
            acc.z -= a * vn.z; acc.w -= a * vn.w;
        }

        const float4* xp = (const float4*)(g_xpm + (size_t)g * CQ);
        float4 xv = xp[lane];
        int c = lane * 4;
        float4 hv;
        hv.x = f2tff((xv.x + acc.x) * s_scale[c + 0] + s_shift[c + 0]);
        hv.y = f2tff((xv.y + acc.y) * s_scale[c + 1] + s_shift[c + 1]);
        hv.z = f2tff((xv.z + acc.z) * s_scale[c + 2] + s_shift[c + 2]);
        hv.w = f2tff((xv.w + acc.w) * s_scale[c + 3] + s_shift[c + 3]);
        ((float4*)(g_h + (size_t)g * CQ))[lane] = hv;
    }
}

// K5: y = W2 @ hid, channel-major into d_out at channel offset 4.
__global__ void __launch_bounds__(256) k_gemm_w2(float* __restrict__ out)
{
    int b = blockIdx.z;
    int p0 = blockIdx.x * 128;

    float acc[4][4][4] = {};
    gemm_core<HIDQ>(g_hid + (size_t)(b * PQ + p0) * HIDQ, g_w2, acc, threadIdx.x);

    const int lane = threadIdx.x & 31, wid = threadIdx.x >> 5;
    const int gid = lane >> 2, tig = lane & 3;
    float* ob = out + (size_t)b * OUTC * PQ + (size_t)4 * PQ;
    int rbase = p0 + (wid & 1) * 64;
    int cbase = (wid >> 1) * 32;
#pragma unroll
    for (int mt = 0; mt < 4; mt++) {
        int r = rbase + mt * 16 + gid;
#pragma unroll
        for (int nt = 0; nt < 4; nt++) {
            int c = cbase + nt * 8 + tig * 2;
            ob[(size_t)c * PQ + r]           = acc[mt][nt][0];
            ob[(size_t)(c + 1) * PQ + r]     = acc[mt][nt][1];
            ob[(size_t)c * PQ + r + 8]       = acc[mt][nt][2];
            ob[(size_t)(c + 1) * PQ + r + 8] = acc[mt][nt][3];
        }
    }
}

// ---------------------------------------------------------------------------
extern "C" void kernel_launch(void* const* d_in, const int* in_sizes, int n_in,
                              void* d_out, int out_size)
{
    const float* x     = (const float*)d_in[0];
    const float* Wq    = (const float*)d_in[1];
    const float* Wk    = (const float*)d_in[2];
    const float* Wv    = (const float*)d_in[3];
    const float* W1    = (const float*)d_in[4];
    const float* W2    = (const float*)d_in[5];
    const float* gamma = (const float*)d_in[6];
    const float* beta  = (const float*)d_in[7];
    const float* mean  = (const float*)d_in[8];
    const float* var   = (const float*)d_in[9];
    float* out = (float*)d_out;

    static cudaStream_t s2;
    static cudaEvent_t evFork, evJoin;
    static int init_done = 0;
    if (!init_done) {
        cudaFuncSetAttribute(k_gemm_qkv, cudaFuncAttributeMaxDynamicSharedMemorySize, ARES_SMEM);
        cudaFuncSetAttribute(k_gemm_w1,  cudaFuncAttributeMaxDynamicSharedMemorySize, ARES_SMEM);
        cudaFuncSetAttribute(k_gemm_qkv, cudaFuncAttributePreferredSharedMemoryCarveout, 100);
        cudaFuncSetAttribute(k_gemm_w1,  cudaFuncAttributePreferredSharedMemoryCarveout, 100);
        cudaFuncSetAttribute(k_gemm_w2,  cudaFuncAttributePreferredSharedMemoryCarveout, 100);
        cudaStreamCreateWithFlags(&s2, cudaStreamNonBlocking);
        cudaEventCreateWithFlags(&evFork, cudaEventDisableTiming);
        cudaEventCreateWithFlags(&evJoin, cudaEventDisableTiming);
        init_done = 1;
    }

    // Fork: topk depends only on x — run it concurrent with roundw/transpose/qkv.
    cudaEventRecord(evFork, 0);
    cudaStreamWaitEvent(s2, evFork, 0);
    k_topk<<<dim3(TQ, BQ, 8), 256, 0, s2>>>(x);
    cudaEventRecord(evJoin, s2);

    k_roundw<<<256, 256>>>(Wq, Wk, Wv, W1, W2);
    k_transpose<<<dim3(PQ / 32, CQ / 32, BQ), dim3(32, 8)>>>(x, out);
    k_gemm_qkv<<<dim3(PQ / 128, BQ), 256, ARES_SMEM>>>();

    // Join: attn needs both g_qkv (default stream) and g_idx (s2).
    cudaStreamWaitEvent(0, evJoin, 0);

    k_attn<<<dim3((BQ * PQ) / 64, 1, 1), 256>>>(gamma, beta, mean, var);
    k_gemm_w1<<<dim3(PQ / 128, BQ), 256, ARES_SMEM>>>();
    k_gemm_w2<<<dim3(PQ / 128, 1, BQ), 256>>>(out);
}